// round 13
// baseline (speedup 1.0000x reference)
#include <cuda_runtime.h>
#include <math.h>

// ---------------------------------------------------------------------------
// Shapes
// B=16, H=W=256, C=1, LOC_C=31
// x1: 16x128x128x8   x2: 16x64x64x16   x3: 16x32x32x31
// feat = 31744 = 992*32 = 496*64 ; out: 16x256x256x32
// ---------------------------------------------------------------------------

#define BN_EPS 1e-3f

__device__ __align__(256) float g_x1[16 * 128 * 128 * 8];     // 8 MB
__device__ __align__(256) float g_x2[16 * 64 * 64 * 16];      // 4 MB
__device__ __align__(256) float g_x3[16 * 32 * 32 * 31];      // 2 MB
__device__ __align__(256) float g_x3p[16 * 32 * 32 * 32];     // 2 MB
__device__ __align__(256) float g_part[992 * 16 * 64];        // 4 MB
__device__ __align__(256) float g_theta[16 * 6];

// ---- packed f32x2 helpers (Blackwell FFMA2) --------------------------------
__device__ __forceinline__ unsigned long long pk2(float a, float b) {
    unsigned long long r;
    asm("mov.b64 %0, {%1, %2};" : "=l"(r) : "f"(a), "f"(b));
    return r;
}
__device__ __forceinline__ void fma2(unsigned long long& d,
                                     unsigned long long a, unsigned long long b) {
    asm("fma.rn.f32x2 %0, %1, %2, %0;" : "+l"(d) : "l"(a), "l"(b));
}
__device__ __forceinline__ float2 upk2(unsigned long long v) {
    float2 r;
    asm("mov.b64 {%0, %1}, %2;" : "=f"(r.x), "=f"(r.y) : "l"(v));
    return r;
}

// ---------------------------------------------------------------------------
// K1: conv1 (3x3, 1->8, SAME) + ReLU + maxpool2  -> g_x1
// ---------------------------------------------------------------------------
__global__ __launch_bounds__(256) void k_conv1(
    const float* __restrict__ x,
    const float* __restrict__ k1,
    const float* __restrict__ b1)
{
    __shared__ float s_x[34 * 34];
    __shared__ __align__(16) float s_w[72];
    __shared__ float s_b[8];
    int tid = threadIdx.x;
    int bidx = blockIdx.x;
    int b  = bidx >> 6;
    int t  = bidx & 63;
    int ty0 = (t >> 3) * 16;
    int tx0 = (t & 7) * 16;

    if (tid < 72) s_w[tid] = k1[tid];
    if (tid < 8)  s_b[tid] = b1[tid];

    const float* xb = x + b * 65536;
    int iy0 = 2 * ty0 - 1, ix0 = 2 * tx0 - 1;
    for (int p = tid; p < 34 * 34; p += 256) {
        int r = p / 34, c = p % 34;
        int gy = iy0 + r, gx = ix0 + c;
        s_x[p] = (gy >= 0 && gy < 256 && gx >= 0 && gx < 256)
                 ? xb[gy * 256 + gx] : 0.f;
    }
    __syncthreads();

    int ly = tid >> 4, lx = tid & 15;

    float win[4][4];
#pragma unroll
    for (int r = 0; r < 4; r++)
#pragma unroll
        for (int c = 0; c < 4; c++)
            win[r][c] = s_x[(2 * ly + r) * 34 + (2 * lx + c)];

    unsigned long long acc2[4][4];
#pragma unroll
    for (int p = 0; p < 4; p++)
#pragma unroll
        for (int k = 0; k < 4; k++) acc2[p][k] = 0ull;

#pragma unroll
    for (int ky = 0; ky < 3; ky++) {
#pragma unroll
        for (int kx = 0; kx < 3; kx++) {
            ulonglong2 wa = *(const ulonglong2*)&s_w[(ky * 3 + kx) * 8];
            ulonglong2 wb = *(const ulonglong2*)&s_w[(ky * 3 + kx) * 8 + 4];
#pragma unroll
            for (int dy = 0; dy < 2; dy++) {
#pragma unroll
                for (int dx = 0; dx < 2; dx++) {
                    float v = win[dy + ky][dx + kx];
                    unsigned long long vv = pk2(v, v);
                    int p = dy * 2 + dx;
                    fma2(acc2[p][0], vv, wa.x);
                    fma2(acc2[p][1], vv, wa.y);
                    fma2(acc2[p][2], vv, wb.x);
                    fma2(acc2[p][3], vv, wb.y);
                }
            }
        }
    }

    float o[8];
#pragma unroll
    for (int k = 0; k < 4; k++) {
        float2 p0 = upk2(acc2[0][k]), p1 = upk2(acc2[1][k]);
        float2 p2 = upk2(acc2[2][k]), p3 = upk2(acc2[3][k]);
        float mx = fmaxf(fmaxf(p0.x, p1.x), fmaxf(p2.x, p3.x));
        float my = fmaxf(fmaxf(p0.y, p1.y), fmaxf(p2.y, p3.y));
        o[2 * k]     = fmaxf(mx + s_b[2 * k], 0.f);
        o[2 * k + 1] = fmaxf(my + s_b[2 * k + 1], 0.f);
    }
    int py = ty0 + ly, px = tx0 + lx;
    float* op = g_x1 + ((size_t)(b * 128 + py) * 128 + px) * 8;
    *(float4*)op       = make_float4(o[0], o[1], o[2], o[3]);
    *(float4*)(op + 4) = make_float4(o[4], o[5], o[6], o[7]);
}

// ---------------------------------------------------------------------------
// K2: conv2 (3x3, 8->16) + ReLU + pool -> g_x2
// 512 blocks x 512 threads: (batch, 8x16 tile). Thread = (pixel, 8-co, dy-half).
// Pool recombined across the dy-half pair via 4 shfl_xor(1).
// ---------------------------------------------------------------------------
__global__ __launch_bounds__(512) void k_conv2(
    const float* __restrict__ k2,      // (3,3,8,16)
    const float* __restrict__ b2)      // (16,)
{
    __shared__ __align__(16) float s_in[18 * 34 * 8];  // 4896 floats
    __shared__ __align__(16) float s_w[1152];
    __shared__ float s_b[16];

    int tid = threadIdx.x;
    int bidx = blockIdx.x;
    int b  = bidx >> 5;
    int t  = bidx & 31;                 // 8 ty x 4 tx
    int ty0 = (t >> 2) * 8;
    int tx0 = (t & 3) * 16;

    for (int i = tid; i < 1152; i += 512) s_w[i] = k2[i];
    if (tid < 16) s_b[tid] = b2[tid];

    int iy0 = 2 * ty0 - 1, ix0 = 2 * tx0 - 1;
    for (int p = tid; p < 18 * 34; p += 512) {
        int r = p / 34, c = p % 34;
        int gy = iy0 + r, gx = ix0 + c;
        float* dst = &s_in[p * 8];
        if (gy >= 0 && gy < 128 && gx >= 0 && gx < 128) {
            const float* src = g_x1 + ((size_t)(b * 128 + gy) * 128 + gx) * 8;
            *(float4*)dst       = *(const float4*)src;
            *(float4*)(dst + 4) = *(const float4*)(src + 4);
        } else {
            *(float4*)dst       = make_float4(0, 0, 0, 0);
            *(float4*)(dst + 4) = make_float4(0, 0, 0, 0);
        }
    }
    __syncthreads();

    int h   = tid & 1;                  // dy half
    int cog = (tid >> 1) & 1, cb = cog * 8;
    int pix = tid >> 2;                 // 0..127
    int ly = pix >> 4, lx = pix & 15;

    unsigned long long acc2[2][4];      // [dx][co-pair of 8]
#pragma unroll
    for (int p = 0; p < 2; p++)
#pragma unroll
        for (int k = 0; k < 4; k++) acc2[p][k] = 0ull;

#pragma unroll
    for (int ky = 0; ky < 3; ky++) {
#pragma unroll
        for (int kx = 0; kx < 3; kx++) {
            const float* wtap = &s_w[(ky * 3 + kx) * 128 + cb];
#pragma unroll
            for (int ciq = 0; ciq < 2; ciq++) {
                float iv[2][4];
#pragma unroll
                for (int dx = 0; dx < 2; dx++) {
                    float4 v = *(const float4*)&s_in[
                        ((2 * ly + h + ky) * 34 + (2 * lx + dx + kx)) * 8 + ciq * 4];
                    iv[dx][0] = v.x; iv[dx][1] = v.y; iv[dx][2] = v.z; iv[dx][3] = v.w;
                }
#pragma unroll
                for (int c = 0; c < 4; c++) {
                    ulonglong2 w0 = *(const ulonglong2*)(wtap + (ciq * 4 + c) * 16);
                    ulonglong2 w1 = *(const ulonglong2*)(wtap + (ciq * 4 + c) * 16 + 4);
#pragma unroll
                    for (int dx = 0; dx < 2; dx++) {
                        unsigned long long vv = pk2(iv[dx][c], iv[dx][c]);
                        fma2(acc2[dx][0], vv, w0.x);
                        fma2(acc2[dx][1], vv, w0.y);
                        fma2(acc2[dx][2], vv, w1.x);
                        fma2(acc2[dx][3], vv, w1.y);
                    }
                }
            }
        }
    }

    // max over dx within thread -> m[8] for this dy half
    float m[8];
#pragma unroll
    for (int k = 0; k < 4; k++) {
        float2 p0 = upk2(acc2[0][k]), p1 = upk2(acc2[1][k]);
        m[2 * k]     = fmaxf(p0.x, p1.x);
        m[2 * k + 1] = fmaxf(p0.y, p1.y);
    }
    // exchange with dy partner (tid^1): keep co[4h..4h+3]
    float o[4];
#pragma unroll
    for (int k = 0; k < 4; k++) {
        float sent = (h == 0) ? m[k + 4] : m[k];
        float recv = __shfl_xor_sync(0xFFFFFFFFu, sent, 1);
        float own  = (h == 0) ? m[k] : m[k + 4];
        o[k] = fmaxf(fmaxf(own, recv) + s_b[cb + 4 * h + k], 0.f);
    }

    int py = ty0 + ly, px = tx0 + lx;
    float* op = g_x2 + ((size_t)(b * 64 + py) * 64 + px) * 16 + cb + 4 * h;
    *(float4*)op = make_float4(o[0], o[1], o[2], o[3]);
}

// ---------------------------------------------------------------------------
// K3: conv3 (3x3, 16->31) + ReLU + pool -> g_x3 (packed) + g_x3p (padded)
// 512 blocks x 512 threads: (batch, 4x8 tile). Thread = (pixel, 8-co, pool pos).
// Pool recombined via 2-step shfl_xor (dx then dy).
// ---------------------------------------------------------------------------
__global__ __launch_bounds__(512) void k_conv3(
    const float* __restrict__ k3,      // (3,3,16,31)
    const float* __restrict__ b3)      // (31,)
{
    __shared__ __align__(16) float s_in[10 * 19 * 16];  // padded row stride 19
    __shared__ __align__(16) float s_w[9 * 16 * 32];    // co padded to 32
    __shared__ float s_b[32];

    int tid = threadIdx.x;
    int bidx = blockIdx.x;
    int b  = bidx >> 5;
    int t  = bidx & 31;                 // 8 ty x 4 tx
    int ty0 = (t >> 2) * 4;
    int tx0 = (t & 3) * 8;

    for (int i = tid; i < 4608; i += 512) {
        int tap = i >> 9;
        int rem = i & 511;
        int ci = rem >> 5, co = rem & 31;
        s_w[i] = (co < 31) ? k3[tap * 496 + ci * 31 + co] : 0.f;
    }
    if (tid < 32) s_b[tid] = (tid < 31) ? b3[tid] : 0.f;

    int iy0 = 2 * ty0 - 1, ix0 = 2 * tx0 - 1;
    for (int p = tid; p < 10 * 18; p += 512) {
        int r = p / 18, c = p % 18;
        int gy = iy0 + r, gx = ix0 + c;
        float* dst = &s_in[(r * 19 + c) * 16];
        if (gy >= 0 && gy < 64 && gx >= 0 && gx < 64) {
            const float* src = g_x2 + ((size_t)(b * 64 + gy) * 64 + gx) * 16;
#pragma unroll
            for (int q = 0; q < 4; q++)
                *(float4*)(dst + q * 4) = *(const float4*)(src + q * 4);
        } else {
#pragma unroll
            for (int q = 0; q < 4; q++)
                *(float4*)(dst + q * 4) = make_float4(0, 0, 0, 0);
        }
    }
    __syncthreads();

    int dxp = tid & 1, dyp = (tid >> 1) & 1;
    int cog = (tid >> 2) & 3, cb = cog * 8;
    int pix = tid >> 4;                 // 0..31
    int ly = pix >> 3, lx = pix & 7;

    unsigned long long acc2[4];
#pragma unroll
    for (int k = 0; k < 4; k++) acc2[k] = 0ull;

#pragma unroll
    for (int ky = 0; ky < 3; ky++) {
#pragma unroll
        for (int kx = 0; kx < 3; kx++) {
            const float* wtap = &s_w[(ky * 3 + kx) * 512 + cb];
#pragma unroll
            for (int ciq = 0; ciq < 4; ciq++) {
                float4 v = *(const float4*)&s_in[
                    ((2 * ly + dyp + ky) * 19 + (2 * lx + dxp + kx)) * 16 + ciq * 4];
                float iv[4] = {v.x, v.y, v.z, v.w};
#pragma unroll
                for (int c = 0; c < 4; c++) {
                    ulonglong2 w0 = *(const ulonglong2*)(wtap + (ciq * 4 + c) * 32);
                    ulonglong2 w1 = *(const ulonglong2*)(wtap + (ciq * 4 + c) * 32 + 4);
                    unsigned long long vv = pk2(iv[c], iv[c]);
                    fma2(acc2[0], vv, w0.x);
                    fma2(acc2[1], vv, w0.y);
                    fma2(acc2[2], vv, w1.x);
                    fma2(acc2[3], vv, w1.y);
                }
            }
        }
    }

    float m[8];
#pragma unroll
    for (int k = 0; k < 4; k++) {
        float2 p = upk2(acc2[k]);
        m[2 * k] = p.x; m[2 * k + 1] = p.y;
    }
    // step 1: exchange over dx (xor 1), keep co[4*dxp .. 4*dxp+3]
    float mm[4];
#pragma unroll
    for (int k = 0; k < 4; k++) {
        float sent = (dxp == 0) ? m[k + 4] : m[k];
        float recv = __shfl_xor_sync(0xFFFFFFFFu, sent, 1);
        float own  = (dxp == 0) ? m[k] : m[k + 4];
        mm[k] = fmaxf(own, recv);
    }
    // step 2: exchange over dy (xor 2), full (partner holds same co-set)
#pragma unroll
    for (int k = 0; k < 4; k++)
        mm[k] = fmaxf(mm[k], __shfl_xor_sync(0xFFFFFFFFu, mm[k], 2));

    if (dyp == 0) {
        int py = ty0 + ly, px = tx0 + lx;
        int cell = (b * 32 + py) * 32 + px;
        float* op  = g_x3  + (size_t)cell * 31;
        float* opp = g_x3p + (size_t)cell * 32;
        if (cog == 0 && dxp == 0) opp[0] = 0.f;
#pragma unroll
        for (int k = 0; k < 4; k++) {
            int co = cb + 4 * dxp + k;
            if (co < 31) {
                float v = fmaxf(mm[k] + s_b[co], 0.f);
                op[co] = v;
                opp[co + 1] = v;
            }
        }
    }
}

// ---------------------------------------------------------------------------
// K5: d1 split-K with fused BN. 496 blocks x 256 threads.
// Warp = (32-feature slice, 4-batch group); lane = j-pair (f32x2).
// Weights stream from DRAM as coalesced LDG.64 pairs (used directly as FFMA2
// operands); g staged in smem pre-duplicated as f32x2 (broadcast LDS.64).
// ---------------------------------------------------------------------------
__global__ __launch_bounds__(256) void k_d1(
    const float* __restrict__ d1k,
    const float* __restrict__ gamma, const float* __restrict__ beta,
    const float* __restrict__ mean,  const float* __restrict__ var)
{
    __shared__ unsigned long long gsd[16 * 64];   // 8 KB, duplicated-pair g
    __shared__ float s_sc[64], s_sh[64];
    int tid = threadIdx.x;
    int blk = blockIdx.x;                         // features blk*64 .. +63

    if (tid < 64) {
        int f = blk * 64 + tid;
        float sc = rsqrtf(var[f] + BN_EPS) * gamma[f];
        s_sc[tid] = sc;
        s_sh[tid] = beta[f] - mean[f] * sc;
    }
    __syncthreads();
    for (int i = tid; i < 1024; i += 256) {
        int bb = i >> 6, ff = i & 63;
        float v = g_x3[bb * 31744 + blk * 64 + ff] * s_sc[ff] + s_sh[ff];
        gsd[i] = pk2(v, v);
    }
    __syncthreads();

    int w = tid >> 5, lane = tid & 31;
    int sl = w >> 2;                              // 0/1 : slice p = blk*2+sl
    int bg = w & 3;                               // batches 4bg..4bg+3

    const unsigned long long* wrow =
        (const unsigned long long*)(d1k + (size_t)(blk * 64 + sl * 32) * 64) + lane;
    const unsigned long long* g0 = &gsd[(4 * bg + 0) * 64 + sl * 32];
    const unsigned long long* g1 = &gsd[(4 * bg + 1) * 64 + sl * 32];
    const unsigned long long* g2 = &gsd[(4 * bg + 2) * 64 + sl * 32];
    const unsigned long long* g3 = &gsd[(4 * bg + 3) * 64 + sl * 32];

    unsigned long long a0 = 0, a1 = 0, a2 = 0, a3 = 0;
#pragma unroll 8
    for (int f = 0; f < 32; f++) {
        unsigned long long wv = wrow[(size_t)f * 32];
        fma2(a0, g0[f], wv);
        fma2(a1, g1[f], wv);
        fma2(a2, g2[f], wv);
        fma2(a3, g3[f], wv);
    }

    int p = blk * 2 + sl;
    size_t base = ((size_t)p * 16 + 4 * bg) * 64 + 2 * lane;
    *(float2*)&g_part[base]       = upk2(a0);
    *(float2*)&g_part[base + 64]  = upk2(a1);
    *(float2*)&g_part[base + 128] = upk2(a2);
    *(float2*)&g_part[base + 192] = upk2(a3);
}

// ---------------------------------------------------------------------------
// K6: fused head — vectorized reduce of d1 partials + bias + relu, d2, d3.
// One block per batch. Stage 1: thread = (j-quad, p-group of 16), float4 loads.
// ---------------------------------------------------------------------------
__global__ __launch_bounds__(256) void k_head(
    const float* __restrict__ d1b,
    const float* __restrict__ d2k, const float* __restrict__ d2b,
    const float* __restrict__ d3k, const float* __restrict__ d3b)
{
    __shared__ float s_red[16 * 16 * 4];   // [grp][j4][4]
    __shared__ float h1s[64];
    __shared__ float h2s[96];
    int tid = threadIdx.x;
    int b = blockIdx.x;
    int j4 = tid & 15, grp = tid >> 4;

    float4 s = make_float4(0.f, 0.f, 0.f, 0.f);
#pragma unroll 8
    for (int p = grp; p < 992; p += 16) {
        float4 v = *(const float4*)&g_part[((size_t)p * 16 + b) * 64 + 4 * j4];
        s.x += v.x; s.y += v.y; s.z += v.z; s.w += v.w;
    }
    *(float4*)&s_red[tid * 4] = s;
    __syncthreads();

    if (tid < 64) {
        int jj4 = tid >> 2, c = tid & 3;
        float v = 0.f;
#pragma unroll
        for (int g = 0; g < 16; g++) v += s_red[(g * 16 + jj4) * 4 + c];
        h1s[tid] = fmaxf(v + d1b[tid], 0.f);
    }
    __syncthreads();

    if (tid < 96) {
        float v = d2b[tid];
#pragma unroll 8
        for (int i = 0; i < 64; i++) v += h1s[i] * d2k[i * 96 + tid];
        h2s[tid] = fmaxf(v, 0.f);
    }
    __syncthreads();

    if (tid < 6) {
        float v = d3b[tid];
#pragma unroll 8
        for (int k = 0; k < 96; k++) v += h2s[k] * d3k[k * 6 + tid];
        g_theta[b * 6 + tid] = v;
    }
}

// ---------------------------------------------------------------------------
// K7: fused grid-gen + bilinear sampler + leaky relu.
// Block = 32 px along x, 4 consecutive rows. 8 lanes per pixel (channel quads).
// ---------------------------------------------------------------------------
__global__ __launch_bounds__(256) void k_sampler(
    const float* __restrict__ x,       // (16,256,256,1)
    float* __restrict__ out)           // (16,256,256,32)
{
    int bidx = blockIdx.x;             // 8192 = 16 b x 64 row-groups x 8 col-groups
    int b   = bidx >> 9;
    int r   = bidx & 511;
    int oy0 = (r >> 3) * 4;
    int ox0 = (r & 7) * 32;
    int tid = threadIdx.x;
    int tq = tid & 7;
    int pp = tid >> 3;
    int ox = ox0 + pp;

    float th0 = g_theta[b * 6 + 0];
    float th1 = g_theta[b * 6 + 1];
    float th2 = g_theta[b * 6 + 2];
    float th3 = g_theta[b * 6 + 3];
    float th4 = g_theta[b * 6 + 4];
    float th5 = g_theta[b * 6 + 5];

    float gx = ((float)ox / 255.f) * 2.f - 1.f;
    const float* xb = x + (size_t)b * 65536;
    const float* xp = g_x3p + (size_t)b * 32768 + 4 * tq;

#pragma unroll
    for (int rr = 0; rr < 4; rr++) {
        int oy = oy0 + rr;
        float gy = ((float)oy / 255.f) * 2.f - 1.f;
        float tgx = gx * th0 + gy * th3 + th2;
        float tgy = gx * th1 + gy * th4 + th5;

        float fx = 0.5f * ((tgx + 1.f) * 255.f);
        float fy = 0.5f * ((tgy + 1.f) * 255.f);
        float x0f = floorf(fx), x1f = x0f + 1.f;
        float y0f = floorf(fy), y1f = y0f + 1.f;
        x0f = fminf(fmaxf(x0f, 0.f), 255.f);
        x1f = fminf(fmaxf(x1f, 0.f), 255.f);
        y0f = fminf(fmaxf(y0f, 0.f), 255.f);
        y1f = fminf(fmaxf(y1f, 0.f), 255.f);
        float wa = (x1f - fx) * (y1f - fy);
        float wb = (x1f - fx) * (fy - y0f);
        float wc = (fx - x0f) * (y1f - fy);
        float wd = (fx - x0f) * (fy - y0f);
        int xi0 = (int)x0f, xi1 = (int)x1f, yi0 = (int)y0f, yi1 = (int)y1f;

        int cy0 = yi0 >> 3, cy1 = yi1 >> 3, cx0 = xi0 >> 3, cx1 = xi1 >> 3;

        float4 va = *(const float4*)(xp + (cy0 * 32 + cx0) * 32);
        float4 vb = *(const float4*)(xp + (cy1 * 32 + cx0) * 32);
        float4 vc = *(const float4*)(xp + (cy0 * 32 + cx1) * 32);
        float4 vd = *(const float4*)(xp + (cy1 * 32 + cx1) * 32);

        float4 val;
        val.x = wa * va.x + wb * vb.x + wc * vc.x + wd * vd.x;
        val.y = wa * va.y + wb * vb.y + wc * vc.y + wd * vd.y;
        val.z = wa * va.z + wb * vb.z + wc * vc.z + wd * vd.z;
        val.w = wa * va.w + wb * vb.w + wc * vc.w + wd * vd.w;

        if (tq == 0) {
            val.x = wa * xb[yi0 * 256 + xi0] + wb * xb[yi1 * 256 + xi0]
                  + wc * xb[yi0 * 256 + xi1] + wd * xb[yi1 * 256 + xi1];
        }

        val.x = (val.x >= 0.f) ? val.x : 0.1f * val.x;
        val.y = (val.y >= 0.f) ? val.y : 0.1f * val.y;
        val.z = (val.z >= 0.f) ? val.z : 0.1f * val.z;
        val.w = (val.w >= 0.f) ? val.w : 0.1f * val.w;

        *(float4*)(out + (((size_t)(b * 256 + oy)) * 256 + ox) * 32 + 4 * tq) = val;
    }
}

// ---------------------------------------------------------------------------
// Launch
// ---------------------------------------------------------------------------
extern "C" void kernel_launch(void* const* d_in, const int* in_sizes, int n_in,
                              void* d_out, int out_size)
{
    const float* x       = (const float*)d_in[0];
    const float* conv1_k = (const float*)d_in[1];
    const float* conv1_b = (const float*)d_in[2];
    const float* conv2_k = (const float*)d_in[3];
    const float* conv2_b = (const float*)d_in[4];
    const float* conv3_k = (const float*)d_in[5];
    const float* conv3_b = (const float*)d_in[6];
    const float* bn_gamma = (const float*)d_in[7];
    const float* bn_beta  = (const float*)d_in[8];
    const float* bn_mean  = (const float*)d_in[9];
    const float* bn_var   = (const float*)d_in[10];
    const float* d1_k = (const float*)d_in[11];
    const float* d1_b = (const float*)d_in[12];
    const float* d2_k = (const float*)d_in[13];
    const float* d2_b = (const float*)d_in[14];
    const float* d3_k = (const float*)d_in[15];
    const float* d3_b = (const float*)d_in[16];
    float* out = (float*)d_out;

    k_conv1<<<1024, 256>>>(x, conv1_k, conv1_b);
    k_conv2<<<512, 512>>>(conv2_k, conv2_b);
    k_conv3<<<512, 512>>>(conv3_k, conv3_b);
    k_d1<<<496, 256>>>(d1_k, bn_gamma, bn_beta, bn_mean, bn_var);
    k_head<<<16, 256>>>(d1_b, d2_k, d2_b, d3_k, d3_b);
    k_sampler<<<8192, 256>>>(x, out);
}

// round 14
// speedup vs baseline: 1.1253x; 1.1253x over previous
#include <cuda_runtime.h>
#include <math.h>

// ---------------------------------------------------------------------------
// Shapes
// B=16, H=W=256, C=1, LOC_C=31
// x1: 16x128x128x8   x2: 16x64x64x16   x3: 16x32x32x31
// feat = 31744 = 992*32 ; out: 16x256x256x32
// ---------------------------------------------------------------------------

#define BN_EPS 1e-3f

__device__ __align__(256) float g_x1[16 * 128 * 128 * 8];     // 8 MB
__device__ __align__(256) float g_x2[16 * 64 * 64 * 16];      // 4 MB
__device__ __align__(256) float g_x3[16 * 32 * 32 * 31];      // 2 MB
__device__ __align__(256) float g_x3p[16 * 32 * 32 * 32];     // 2 MB
__device__ __align__(256) float g_part[992 * 16 * 64];        // 4 MB
__device__ __align__(256) float g_theta[16 * 6];

// ---- packed f32x2 helpers (Blackwell FFMA2) --------------------------------
__device__ __forceinline__ unsigned long long pk2(float a, float b) {
    unsigned long long r;
    asm("mov.b64 %0, {%1, %2};" : "=l"(r) : "f"(a), "f"(b));
    return r;
}
__device__ __forceinline__ void fma2(unsigned long long& d,
                                     unsigned long long a, unsigned long long b) {
    asm("fma.rn.f32x2 %0, %1, %2, %0;" : "+l"(d) : "l"(a), "l"(b));
}
__device__ __forceinline__ float2 upk2(unsigned long long v) {
    float2 r;
    asm("mov.b64 {%0, %1}, %2;" : "=f"(r.x), "=f"(r.y) : "l"(v));
    return r;
}

// ---------------------------------------------------------------------------
// K1: conv1 (3x3, 1->8, SAME) + ReLU + maxpool2  -> g_x1
// Block = (batch, 16x16 pooled tile). Packed f32x2 accumulation (co pairs).
// ---------------------------------------------------------------------------
__global__ __launch_bounds__(256) void k_conv1(
    const float* __restrict__ x,
    const float* __restrict__ k1,
    const float* __restrict__ b1)
{
    __shared__ float s_x[34 * 34];
    __shared__ __align__(16) float s_w[72];
    __shared__ float s_b[8];
    int tid = threadIdx.x;
    int bidx = blockIdx.x;
    int b  = bidx >> 6;
    int t  = bidx & 63;
    int ty0 = (t >> 3) * 16;
    int tx0 = (t & 7) * 16;

    if (tid < 72) s_w[tid] = k1[tid];
    if (tid < 8)  s_b[tid] = b1[tid];

    const float* xb = x + b * 65536;
    int iy0 = 2 * ty0 - 1, ix0 = 2 * tx0 - 1;
    for (int p = tid; p < 34 * 34; p += 256) {
        int r = p / 34, c = p % 34;
        int gy = iy0 + r, gx = ix0 + c;
        s_x[p] = (gy >= 0 && gy < 256 && gx >= 0 && gx < 256)
                 ? xb[gy * 256 + gx] : 0.f;
    }
    __syncthreads();

    int ly = tid >> 4, lx = tid & 15;

    float win[4][4];
#pragma unroll
    for (int r = 0; r < 4; r++)
#pragma unroll
        for (int c = 0; c < 4; c++)
            win[r][c] = s_x[(2 * ly + r) * 34 + (2 * lx + c)];

    unsigned long long acc2[4][4];
#pragma unroll
    for (int p = 0; p < 4; p++)
#pragma unroll
        for (int k = 0; k < 4; k++) acc2[p][k] = 0ull;

#pragma unroll
    for (int ky = 0; ky < 3; ky++) {
#pragma unroll
        for (int kx = 0; kx < 3; kx++) {
            ulonglong2 wa = *(const ulonglong2*)&s_w[(ky * 3 + kx) * 8];
            ulonglong2 wb = *(const ulonglong2*)&s_w[(ky * 3 + kx) * 8 + 4];
#pragma unroll
            for (int dy = 0; dy < 2; dy++) {
#pragma unroll
                for (int dx = 0; dx < 2; dx++) {
                    float v = win[dy + ky][dx + kx];
                    unsigned long long vv = pk2(v, v);
                    int p = dy * 2 + dx;
                    fma2(acc2[p][0], vv, wa.x);
                    fma2(acc2[p][1], vv, wa.y);
                    fma2(acc2[p][2], vv, wb.x);
                    fma2(acc2[p][3], vv, wb.y);
                }
            }
        }
    }

    float o[8];
#pragma unroll
    for (int k = 0; k < 4; k++) {
        float2 p0 = upk2(acc2[0][k]), p1 = upk2(acc2[1][k]);
        float2 p2 = upk2(acc2[2][k]), p3 = upk2(acc2[3][k]);
        float mx = fmaxf(fmaxf(p0.x, p1.x), fmaxf(p2.x, p3.x));
        float my = fmaxf(fmaxf(p0.y, p1.y), fmaxf(p2.y, p3.y));
        o[2 * k]     = fmaxf(mx + s_b[2 * k], 0.f);
        o[2 * k + 1] = fmaxf(my + s_b[2 * k + 1], 0.f);
    }
    int py = ty0 + ly, px = tx0 + lx;
    float* op = g_x1 + ((size_t)(b * 128 + py) * 128 + px) * 8;
    *(float4*)op       = make_float4(o[0], o[1], o[2], o[3]);
    *(float4*)(op + 4) = make_float4(o[4], o[5], o[6], o[7]);
}

// ---------------------------------------------------------------------------
// K2: conv2 (3x3, 8->16) + ReLU + pool -> g_x2
// 512 blocks: (batch, 8x16 pooled tile). Thread = (pixel, 8-co group).
// ---------------------------------------------------------------------------
__global__ __launch_bounds__(256) void k_conv2(
    const float* __restrict__ k2,      // (3,3,8,16)
    const float* __restrict__ b2)      // (16,)
{
    __shared__ __align__(16) float s_in[18 * 34 * 8];  // 4896 floats
    __shared__ __align__(16) float s_w[1152];
    __shared__ float s_b[16];

    int tid = threadIdx.x;
    int bidx = blockIdx.x;
    int b  = bidx >> 5;
    int t  = bidx & 31;                 // 8 ty-tiles x 4 tx-tiles
    int ty0 = (t >> 2) * 8;
    int tx0 = (t & 3) * 16;

    for (int i = tid; i < 1152; i += 256) s_w[i] = k2[i];
    if (tid < 16) s_b[tid] = b2[tid];

    int iy0 = 2 * ty0 - 1, ix0 = 2 * tx0 - 1;
    for (int p = tid; p < 18 * 34; p += 256) {
        int r = p / 34, c = p % 34;
        int gy = iy0 + r, gx = ix0 + c;
        float* dst = &s_in[p * 8];
        if (gy >= 0 && gy < 128 && gx >= 0 && gx < 128) {
            const float* src = g_x1 + ((size_t)(b * 128 + gy) * 128 + gx) * 8;
            *(float4*)dst       = *(const float4*)src;
            *(float4*)(dst + 4) = *(const float4*)(src + 4);
        } else {
            *(float4*)dst       = make_float4(0, 0, 0, 0);
            *(float4*)(dst + 4) = make_float4(0, 0, 0, 0);
        }
    }
    __syncthreads();

    int pix = tid >> 1, cog = tid & 1, cb = cog * 8;
    int ly = pix >> 4, lx = pix & 15;

    unsigned long long acc2[4][4];     // [pos][co-pair of 8]
#pragma unroll
    for (int p = 0; p < 4; p++)
#pragma unroll
        for (int k = 0; k < 4; k++) acc2[p][k] = 0ull;

#pragma unroll
    for (int ky = 0; ky < 3; ky++) {
#pragma unroll
        for (int kx = 0; kx < 3; kx++) {
            const float* wtap = &s_w[(ky * 3 + kx) * 128 + cb];
#pragma unroll
            for (int ciq = 0; ciq < 2; ciq++) {
                float iv[4][4];
#pragma unroll
                for (int dy = 0; dy < 2; dy++) {
#pragma unroll
                    for (int dx = 0; dx < 2; dx++) {
                        float4 v = *(const float4*)&s_in[
                            ((2 * ly + dy + ky) * 34 + (2 * lx + dx + kx)) * 8 + ciq * 4];
                        int p = dy * 2 + dx;
                        iv[p][0] = v.x; iv[p][1] = v.y; iv[p][2] = v.z; iv[p][3] = v.w;
                    }
                }
#pragma unroll
                for (int c = 0; c < 4; c++) {
                    ulonglong2 w0 = *(const ulonglong2*)(wtap + (ciq * 4 + c) * 16);
                    ulonglong2 w1 = *(const ulonglong2*)(wtap + (ciq * 4 + c) * 16 + 4);
#pragma unroll
                    for (int p = 0; p < 4; p++) {
                        unsigned long long vv = pk2(iv[p][c], iv[p][c]);
                        fma2(acc2[p][0], vv, w0.x);
                        fma2(acc2[p][1], vv, w0.y);
                        fma2(acc2[p][2], vv, w1.x);
                        fma2(acc2[p][3], vv, w1.y);
                    }
                }
            }
        }
    }

    float o[8];
#pragma unroll
    for (int k = 0; k < 4; k++) {
        float2 p0 = upk2(acc2[0][k]), p1 = upk2(acc2[1][k]);
        float2 p2 = upk2(acc2[2][k]), p3 = upk2(acc2[3][k]);
        float mx = fmaxf(fmaxf(p0.x, p1.x), fmaxf(p2.x, p3.x));
        float my = fmaxf(fmaxf(p0.y, p1.y), fmaxf(p2.y, p3.y));
        o[2 * k]     = fmaxf(mx + s_b[cb + 2 * k], 0.f);
        o[2 * k + 1] = fmaxf(my + s_b[cb + 2 * k + 1], 0.f);
    }

    int py = ty0 + ly, px = tx0 + lx;
    float* op = g_x2 + ((size_t)(b * 64 + py) * 64 + px) * 16 + cb;
    *(float4*)op       = make_float4(o[0], o[1], o[2], o[3]);
    *(float4*)(op + 4) = make_float4(o[4], o[5], o[6], o[7]);
}

// ---------------------------------------------------------------------------
// K3: conv3 (3x3, 16->31) + ReLU + pool -> g_x3 (packed) + g_x3p (padded)
// 512 blocks: (batch, 4x8 pooled tile). 128 threads = 32 px x 4 cog (8 co each).
// ---------------------------------------------------------------------------
__global__ __launch_bounds__(128) void k_conv3(
    const float* __restrict__ k3,      // (3,3,16,31)
    const float* __restrict__ b3)      // (31,)
{
    __shared__ __align__(16) float s_in[10 * 18 * 16];  // 2880 floats
    __shared__ __align__(16) float s_w[9 * 16 * 32];    // 4608 floats (co padded)
    __shared__ float s_b[32];

    int tid = threadIdx.x;
    int bidx = blockIdx.x;
    int b  = bidx >> 5;
    int t  = bidx & 31;                 // 8 ty-tiles x 4 tx-tiles
    int ty0 = (t >> 2) * 4;
    int tx0 = (t & 3) * 8;

    for (int i = tid; i < 4608; i += 128) {
        int tap = i >> 9;
        int rem = i & 511;
        int ci = rem >> 5, co = rem & 31;
        s_w[i] = (co < 31) ? k3[tap * 496 + ci * 31 + co] : 0.f;
    }
    if (tid < 32) s_b[tid] = (tid < 31) ? b3[tid] : 0.f;

    int iy0 = 2 * ty0 - 1, ix0 = 2 * tx0 - 1;
    for (int p = tid; p < 10 * 18; p += 128) {
        int r = p / 18, c = p % 18;
        int gy = iy0 + r, gx = ix0 + c;
        float* dst = &s_in[p * 16];
        if (gy >= 0 && gy < 64 && gx >= 0 && gx < 64) {
            const float* src = g_x2 + ((size_t)(b * 64 + gy) * 64 + gx) * 16;
#pragma unroll
            for (int q = 0; q < 4; q++)
                *(float4*)(dst + q * 4) = *(const float4*)(src + q * 4);
        } else {
#pragma unroll
            for (int q = 0; q < 4; q++)
                *(float4*)(dst + q * 4) = make_float4(0, 0, 0, 0);
        }
    }
    __syncthreads();

    int pix = tid >> 2, cog = tid & 3, cb = cog * 8;
    int ly = pix >> 3, lx = pix & 7;

    unsigned long long acc2[4][4];
#pragma unroll
    for (int p = 0; p < 4; p++)
#pragma unroll
        for (int k = 0; k < 4; k++) acc2[p][k] = 0ull;

#pragma unroll
    for (int ky = 0; ky < 3; ky++) {
#pragma unroll
        for (int kx = 0; kx < 3; kx++) {
            const float* wtap = &s_w[(ky * 3 + kx) * 512 + cb];
#pragma unroll
            for (int ciq = 0; ciq < 4; ciq++) {
                float iv[4][4];
#pragma unroll
                for (int dy = 0; dy < 2; dy++) {
#pragma unroll
                    for (int dx = 0; dx < 2; dx++) {
                        float4 v = *(const float4*)&s_in[
                            ((2 * ly + dy + ky) * 18 + (2 * lx + dx + kx)) * 16 + ciq * 4];
                        int p = dy * 2 + dx;
                        iv[p][0] = v.x; iv[p][1] = v.y; iv[p][2] = v.z; iv[p][3] = v.w;
                    }
                }
#pragma unroll
                for (int c = 0; c < 4; c++) {
                    ulonglong2 w0 = *(const ulonglong2*)(wtap + (ciq * 4 + c) * 32);
                    ulonglong2 w1 = *(const ulonglong2*)(wtap + (ciq * 4 + c) * 32 + 4);
#pragma unroll
                    for (int p = 0; p < 4; p++) {
                        unsigned long long vv = pk2(iv[p][c], iv[p][c]);
                        fma2(acc2[p][0], vv, w0.x);
                        fma2(acc2[p][1], vv, w0.y);
                        fma2(acc2[p][2], vv, w1.x);
                        fma2(acc2[p][3], vv, w1.y);
                    }
                }
            }
        }
    }

    float m[8];
#pragma unroll
    for (int k = 0; k < 4; k++) {
        float2 p0 = upk2(acc2[0][k]), p1 = upk2(acc2[1][k]);
        float2 p2 = upk2(acc2[2][k]), p3 = upk2(acc2[3][k]);
        m[2 * k]     = fmaxf(fmaxf(p0.x, p1.x), fmaxf(p2.x, p3.x));
        m[2 * k + 1] = fmaxf(fmaxf(p0.y, p1.y), fmaxf(p2.y, p3.y));
    }

    int py = ty0 + ly, px = tx0 + lx;
    int cell = (b * 32 + py) * 32 + px;
    float* op  = g_x3  + (size_t)cell * 31;
    float* opp = g_x3p + (size_t)cell * 32;
    if (cog == 0) opp[0] = 0.f;
#pragma unroll
    for (int k = 0; k < 8; k++) {
        int co = cb + k;
        if (co < 31) {
            float v = fmaxf(m[k] + s_b[co], 0.f);
            op[co] = v;
            opp[co + 1] = v;
        }
    }
}

// ---------------------------------------------------------------------------
// K5: d1 split-K with fused BN affine. 992 blocks, 32-feature slices.
// (R12 version: cooperative float4 smem staging of weights.)
// ---------------------------------------------------------------------------
__global__ __launch_bounds__(256) void k_d1(
    const float* __restrict__ d1k,
    const float* __restrict__ gamma, const float* __restrict__ beta,
    const float* __restrict__ mean,  const float* __restrict__ var)
{
    __shared__ __align__(16) float ks[32 * 64];   // 8 KB
    __shared__ __align__(16) float gs[16 * 32];   // 2 KB
    __shared__ float s_sc[32], s_sh[32];
    int tid = threadIdx.x;
    int p = blockIdx.x;

    const float4* kbase = (const float4*)(d1k + (size_t)p * 2048);
    float4* ks4 = (float4*)ks;
    ks4[tid]       = kbase[tid];
    ks4[tid + 256] = kbase[tid + 256];

    if (tid < 32) {
        int f = p * 32 + tid;
        float sc = rsqrtf(var[f] + BN_EPS) * gamma[f];
        s_sc[tid] = sc;
        s_sh[tid] = beta[f] - mean[f] * sc;
    }
    __syncthreads();
    for (int i = tid; i < 512; i += 256) {
        int bb = i >> 5, ii = i & 31;
        gs[i] = g_x3[bb * 31744 + p * 32 + ii] * s_sc[ii] + s_sh[ii];
    }
    __syncthreads();

    int j = tid & 63, bq = tid >> 6;
    float a0 = 0.f, a1 = 0.f, a2 = 0.f, a3 = 0.f;
#pragma unroll 8
    for (int i = 0; i < 32; i++) {
        float kv = ks[i * 64 + j];
        a0 += gs[bq * 32 + i]        * kv;
        a1 += gs[(bq + 4) * 32 + i]  * kv;
        a2 += gs[(bq + 8) * 32 + i]  * kv;
        a3 += gs[(bq + 12) * 32 + i] * kv;
    }
    g_part[((size_t)p * 16 + bq)      * 64 + j] = a0;
    g_part[((size_t)p * 16 + bq + 4)  * 64 + j] = a1;
    g_part[((size_t)p * 16 + bq + 8)  * 64 + j] = a2;
    g_part[((size_t)p * 16 + bq + 12) * 64 + j] = a3;
}

// ---------------------------------------------------------------------------
// K6: fused head — vectorized reduce of d1 partials + bias + relu, d2, d3.
// One block per batch. Stage 1: thread = (j-quad, p-group of 16), float4 loads.
// ---------------------------------------------------------------------------
__global__ __launch_bounds__(256) void k_head(
    const float* __restrict__ d1b,
    const float* __restrict__ d2k, const float* __restrict__ d2b,
    const float* __restrict__ d3k, const float* __restrict__ d3b)
{
    __shared__ float s_red[16 * 16 * 4];   // [grp][j4][4]
    __shared__ float h1s[64];
    __shared__ float h2s[96];
    int tid = threadIdx.x;
    int b = blockIdx.x;
    int j4 = tid & 15, grp = tid >> 4;

    float4 s = make_float4(0.f, 0.f, 0.f, 0.f);
#pragma unroll 8
    for (int p = grp; p < 992; p += 16) {
        float4 v = *(const float4*)&g_part[((size_t)p * 16 + b) * 64 + 4 * j4];
        s.x += v.x; s.y += v.y; s.z += v.z; s.w += v.w;
    }
    *(float4*)&s_red[tid * 4] = s;
    __syncthreads();

    if (tid < 64) {
        int jj4 = tid >> 2, c = tid & 3;
        float v = 0.f;
#pragma unroll
        for (int g = 0; g < 16; g++) v += s_red[(g * 16 + jj4) * 4 + c];
        h1s[tid] = fmaxf(v + d1b[tid], 0.f);
    }
    __syncthreads();

    if (tid < 96) {
        float v = d2b[tid];
#pragma unroll 8
        for (int i = 0; i < 64; i++) v += h1s[i] * d2k[i * 96 + tid];
        h2s[tid] = fmaxf(v, 0.f);
    }
    __syncthreads();

    if (tid < 6) {
        float v = d3b[tid];
#pragma unroll 8
        for (int k = 0; k < 96; k++) v += h2s[k] * d3k[k * 6 + tid];
        g_theta[b * 6 + tid] = v;
    }
}

// ---------------------------------------------------------------------------
// K7: fused grid-gen + bilinear sampler + leaky relu.
// Block = 32 px along x, 4 consecutive rows. 8 lanes per pixel (channel quads).
// ---------------------------------------------------------------------------
__global__ __launch_bounds__(256) void k_sampler(
    const float* __restrict__ x,       // (16,256,256,1)
    float* __restrict__ out)           // (16,256,256,32)
{
    int bidx = blockIdx.x;             // 8192 = 16 b x 64 row-groups x 8 col-groups
    int b   = bidx >> 9;
    int r   = bidx & 511;
    int oy0 = (r >> 3) * 4;
    int ox0 = (r & 7) * 32;
    int tid = threadIdx.x;
    int tq = tid & 7;
    int pp = tid >> 3;
    int ox = ox0 + pp;

    float th0 = g_theta[b * 6 + 0];
    float th1 = g_theta[b * 6 + 1];
    float th2 = g_theta[b * 6 + 2];
    float th3 = g_theta[b * 6 + 3];
    float th4 = g_theta[b * 6 + 4];
    float th5 = g_theta[b * 6 + 5];

    float gx = ((float)ox / 255.f) * 2.f - 1.f;
    const float* xb = x + (size_t)b * 65536;
    const float* xp = g_x3p + (size_t)b * 32768 + 4 * tq;

#pragma unroll
    for (int rr = 0; rr < 4; rr++) {
        int oy = oy0 + rr;
        float gy = ((float)oy / 255.f) * 2.f - 1.f;
        float tgx = gx * th0 + gy * th3 + th2;
        float tgy = gx * th1 + gy * th4 + th5;

        float fx = 0.5f * ((tgx + 1.f) * 255.f);
        float fy = 0.5f * ((tgy + 1.f) * 255.f);
        float x0f = floorf(fx), x1f = x0f + 1.f;
        float y0f = floorf(fy), y1f = y0f + 1.f;
        x0f = fminf(fmaxf(x0f, 0.f), 255.f);
        x1f = fminf(fmaxf(x1f, 0.f), 255.f);
        y0f = fminf(fmaxf(y0f, 0.f), 255.f);
        y1f = fminf(fmaxf(y1f, 0.f), 255.f);
        float wa = (x1f - fx) * (y1f - fy);
        float wb = (x1f - fx) * (fy - y0f);
        float wc = (fx - x0f) * (y1f - fy);
        float wd = (fx - x0f) * (fy - y0f);
        int xi0 = (int)x0f, xi1 = (int)x1f, yi0 = (int)y0f, yi1 = (int)y1f;

        int cy0 = yi0 >> 3, cy1 = yi1 >> 3, cx0 = xi0 >> 3, cx1 = xi1 >> 3;

        float4 va = *(const float4*)(xp + (cy0 * 32 + cx0) * 32);
        float4 vb = *(const float4*)(xp + (cy1 * 32 + cx0) * 32);
        float4 vc = *(const float4*)(xp + (cy0 * 32 + cx1) * 32);
        float4 vd = *(const float4*)(xp + (cy1 * 32 + cx1) * 32);

        float4 val;
        val.x = wa * va.x + wb * vb.x + wc * vc.x + wd * vd.x;
        val.y = wa * va.y + wb * vb.y + wc * vc.y + wd * vd.y;
        val.z = wa * va.z + wb * vb.z + wc * vc.z + wd * vd.z;
        val.w = wa * va.w + wb * vb.w + wc * vc.w + wd * vd.w;

        if (tq == 0) {
            val.x = wa * xb[yi0 * 256 + xi0] + wb * xb[yi1 * 256 + xi0]
                  + wc * xb[yi0 * 256 + xi1] + wd * xb[yi1 * 256 + xi1];
        }

        val.x = (val.x >= 0.f) ? val.x : 0.1f * val.x;
        val.y = (val.y >= 0.f) ? val.y : 0.1f * val.y;
        val.z = (val.z >= 0.f) ? val.z : 0.1f * val.z;
        val.w = (val.w >= 0.f) ? val.w : 0.1f * val.w;

        *(float4*)(out + (((size_t)(b * 256 + oy)) * 256 + ox) * 32 + 4 * tq) = val;
    }
}

// ---------------------------------------------------------------------------
// Launch
// ---------------------------------------------------------------------------
extern "C" void kernel_launch(void* const* d_in, const int* in_sizes, int n_in,
                              void* d_out, int out_size)
{
    const float* x       = (const float*)d_in[0];
    const float* conv1_k = (const float*)d_in[1];
    const float* conv1_b = (const float*)d_in[2];
    const float* conv2_k = (const float*)d_in[3];
    const float* conv2_b = (const float*)d_in[4];
    const float* conv3_k = (const float*)d_in[5];
    const float* conv3_b = (const float*)d_in[6];
    const float* bn_gamma = (const float*)d_in[7];
    const float* bn_beta  = (const float*)d_in[8];
    const float* bn_mean  = (const float*)d_in[9];
    const float* bn_var   = (const float*)d_in[10];
    const float* d1_k = (const float*)d_in[11];
    const float* d1_b = (const float*)d_in[12];
    const float* d2_k = (const float*)d_in[13];
    const float* d2_b = (const float*)d_in[14];
    const float* d3_k = (const float*)d_in[15];
    const float* d3_b = (const float*)d_in[16];
    float* out = (float*)d_out;

    k_conv1<<<1024, 256>>>(x, conv1_k, conv1_b);
    k_conv2<<<512, 256>>>(conv2_k, conv2_b);
    k_conv3<<<512, 128>>>(conv3_k, conv3_b);
    k_d1<<<992, 256>>>(d1_k, bn_gamma, bn_beta, bn_mean, bn_var);
    k_head<<<16, 256>>>(d1_b, d2_k, d2_b, d3_k, d3_b);
    k_sampler<<<8192, 256>>>(x, out);
}

// round 15
// speedup vs baseline: 1.1703x; 1.0399x over previous
#include <cuda_runtime.h>
#include <math.h>

// ---------------------------------------------------------------------------
// Shapes
// B=16, H=W=256, C=1, LOC_C=31
// x1: 16x128x128x8   x2: 16x64x64x16   x3: 16x32x32x31
// feat = 31744 = 992*32 ; out: 16x256x256x32
// ---------------------------------------------------------------------------

#define BN_EPS 1e-3f

__device__ __align__(256) float g_x1[16 * 128 * 128 * 8];     // 8 MB
__device__ __align__(256) float g_x2[16 * 64 * 64 * 16];      // 4 MB
__device__ __align__(256) float g_x3[16 * 32 * 32 * 31];      // 2 MB
__device__ __align__(256) float g_x3p[16 * 32 * 32 * 32];     // 2 MB
__device__ __align__(256) float g_part[992 * 16 * 64];        // 4 MB
__device__ __align__(256) float g_theta[16 * 6];

// ---- packed f32x2 helpers (Blackwell FFMA2) --------------------------------
__device__ __forceinline__ unsigned long long pk2(float a, float b) {
    unsigned long long r;
    asm("mov.b64 %0, {%1, %2};" : "=l"(r) : "f"(a), "f"(b));
    return r;
}
__device__ __forceinline__ void fma2(unsigned long long& d,
                                     unsigned long long a, unsigned long long b) {
    asm("fma.rn.f32x2 %0, %1, %2, %0;" : "+l"(d) : "l"(a), "l"(b));
}
__device__ __forceinline__ float2 upk2(unsigned long long v) {
    float2 r;
    asm("mov.b64 {%0, %1}, %2;" : "=f"(r.x), "=f"(r.y) : "l"(v));
    return r;
}

// ---------------------------------------------------------------------------
// K1: conv1 (3x3, 1->8, SAME) + ReLU + maxpool2  -> g_x1
// ---------------------------------------------------------------------------
__global__ __launch_bounds__(256) void k_conv1(
    const float* __restrict__ x,
    const float* __restrict__ k1,
    const float* __restrict__ b1)
{
    __shared__ float s_x[34 * 34];
    __shared__ __align__(16) float s_w[72];
    __shared__ float s_b[8];
    int tid = threadIdx.x;
    int bidx = blockIdx.x;
    int b  = bidx >> 6;
    int t  = bidx & 63;
    int ty0 = (t >> 3) * 16;
    int tx0 = (t & 7) * 16;

    if (tid < 72) s_w[tid] = k1[tid];
    if (tid < 8)  s_b[tid] = b1[tid];

    const float* xb = x + b * 65536;
    int iy0 = 2 * ty0 - 1, ix0 = 2 * tx0 - 1;
    for (int p = tid; p < 34 * 34; p += 256) {
        int r = p / 34, c = p % 34;
        int gy = iy0 + r, gx = ix0 + c;
        s_x[p] = (gy >= 0 && gy < 256 && gx >= 0 && gx < 256)
                 ? xb[gy * 256 + gx] : 0.f;
    }
    __syncthreads();

    int ly = tid >> 4, lx = tid & 15;

    float win[4][4];
#pragma unroll
    for (int r = 0; r < 4; r++)
#pragma unroll
        for (int c = 0; c < 4; c++)
            win[r][c] = s_x[(2 * ly + r) * 34 + (2 * lx + c)];

    unsigned long long acc2[4][4];
#pragma unroll
    for (int p = 0; p < 4; p++)
#pragma unroll
        for (int k = 0; k < 4; k++) acc2[p][k] = 0ull;

#pragma unroll
    for (int ky = 0; ky < 3; ky++) {
#pragma unroll
        for (int kx = 0; kx < 3; kx++) {
            ulonglong2 wa = *(const ulonglong2*)&s_w[(ky * 3 + kx) * 8];
            ulonglong2 wb = *(const ulonglong2*)&s_w[(ky * 3 + kx) * 8 + 4];
#pragma unroll
            for (int dy = 0; dy < 2; dy++) {
#pragma unroll
                for (int dx = 0; dx < 2; dx++) {
                    float v = win[dy + ky][dx + kx];
                    unsigned long long vv = pk2(v, v);
                    int p = dy * 2 + dx;
                    fma2(acc2[p][0], vv, wa.x);
                    fma2(acc2[p][1], vv, wa.y);
                    fma2(acc2[p][2], vv, wb.x);
                    fma2(acc2[p][3], vv, wb.y);
                }
            }
        }
    }

    float o[8];
#pragma unroll
    for (int k = 0; k < 4; k++) {
        float2 p0 = upk2(acc2[0][k]), p1 = upk2(acc2[1][k]);
        float2 p2 = upk2(acc2[2][k]), p3 = upk2(acc2[3][k]);
        float mx = fmaxf(fmaxf(p0.x, p1.x), fmaxf(p2.x, p3.x));
        float my = fmaxf(fmaxf(p0.y, p1.y), fmaxf(p2.y, p3.y));
        o[2 * k]     = fmaxf(mx + s_b[2 * k], 0.f);
        o[2 * k + 1] = fmaxf(my + s_b[2 * k + 1], 0.f);
    }
    int py = ty0 + ly, px = tx0 + lx;
    float* op = g_x1 + ((size_t)(b * 128 + py) * 128 + px) * 8;
    *(float4*)op       = make_float4(o[0], o[1], o[2], o[3]);
    *(float4*)(op + 4) = make_float4(o[4], o[5], o[6], o[7]);
}

// ---------------------------------------------------------------------------
// K2: conv2 (3x3, 8->16) + ReLU + pool -> g_x2  (PDL consumer of conv1)
// ---------------------------------------------------------------------------
__global__ __launch_bounds__(256) void k_conv2(
    const float* __restrict__ k2,      // (3,3,8,16)
    const float* __restrict__ b2)      // (16,)
{
    __shared__ __align__(16) float s_in[18 * 34 * 8];  // 4896 floats
    __shared__ __align__(16) float s_w[1152];
    __shared__ float s_b[16];

    int tid = threadIdx.x;
    int bidx = blockIdx.x;
    int b  = bidx >> 5;
    int t  = bidx & 31;                 // 8 ty-tiles x 4 tx-tiles
    int ty0 = (t >> 2) * 8;
    int tx0 = (t & 3) * 16;

    // independent prologue: weights
    for (int i = tid; i < 1152; i += 256) s_w[i] = k2[i];
    if (tid < 16) s_b[tid] = b2[tid];

    cudaGridDependencySynchronize();   // wait for conv1's g_x1

    int iy0 = 2 * ty0 - 1, ix0 = 2 * tx0 - 1;
    for (int p = tid; p < 18 * 34; p += 256) {
        int r = p / 34, c = p % 34;
        int gy = iy0 + r, gx = ix0 + c;
        float* dst = &s_in[p * 8];
        if (gy >= 0 && gy < 128 && gx >= 0 && gx < 128) {
            const float* src = g_x1 + ((size_t)(b * 128 + gy) * 128 + gx) * 8;
            *(float4*)dst       = *(const float4*)src;
            *(float4*)(dst + 4) = *(const float4*)(src + 4);
        } else {
            *(float4*)dst       = make_float4(0, 0, 0, 0);
            *(float4*)(dst + 4) = make_float4(0, 0, 0, 0);
        }
    }
    __syncthreads();

    int pix = tid >> 1, cog = tid & 1, cb = cog * 8;
    int ly = pix >> 4, lx = pix & 15;

    unsigned long long acc2[4][4];     // [pos][co-pair of 8]
#pragma unroll
    for (int p = 0; p < 4; p++)
#pragma unroll
        for (int k = 0; k < 4; k++) acc2[p][k] = 0ull;

#pragma unroll
    for (int ky = 0; ky < 3; ky++) {
#pragma unroll
        for (int kx = 0; kx < 3; kx++) {
            const float* wtap = &s_w[(ky * 3 + kx) * 128 + cb];
#pragma unroll
            for (int ciq = 0; ciq < 2; ciq++) {
                float iv[4][4];
#pragma unroll
                for (int dy = 0; dy < 2; dy++) {
#pragma unroll
                    for (int dx = 0; dx < 2; dx++) {
                        float4 v = *(const float4*)&s_in[
                            ((2 * ly + dy + ky) * 34 + (2 * lx + dx + kx)) * 8 + ciq * 4];
                        int p = dy * 2 + dx;
                        iv[p][0] = v.x; iv[p][1] = v.y; iv[p][2] = v.z; iv[p][3] = v.w;
                    }
                }
#pragma unroll
                for (int c = 0; c < 4; c++) {
                    ulonglong2 w0 = *(const ulonglong2*)(wtap + (ciq * 4 + c) * 16);
                    ulonglong2 w1 = *(const ulonglong2*)(wtap + (ciq * 4 + c) * 16 + 4);
#pragma unroll
                    for (int p = 0; p < 4; p++) {
                        unsigned long long vv = pk2(iv[p][c], iv[p][c]);
                        fma2(acc2[p][0], vv, w0.x);
                        fma2(acc2[p][1], vv, w0.y);
                        fma2(acc2[p][2], vv, w1.x);
                        fma2(acc2[p][3], vv, w1.y);
                    }
                }
            }
        }
    }

    float o[8];
#pragma unroll
    for (int k = 0; k < 4; k++) {
        float2 p0 = upk2(acc2[0][k]), p1 = upk2(acc2[1][k]);
        float2 p2 = upk2(acc2[2][k]), p3 = upk2(acc2[3][k]);
        float mx = fmaxf(fmaxf(p0.x, p1.x), fmaxf(p2.x, p3.x));
        float my = fmaxf(fmaxf(p0.y, p1.y), fmaxf(p2.y, p3.y));
        o[2 * k]     = fmaxf(mx + s_b[cb + 2 * k], 0.f);
        o[2 * k + 1] = fmaxf(my + s_b[cb + 2 * k + 1], 0.f);
    }

    int py = ty0 + ly, px = tx0 + lx;
    float* op = g_x2 + ((size_t)(b * 64 + py) * 64 + px) * 16 + cb;
    *(float4*)op       = make_float4(o[0], o[1], o[2], o[3]);
    *(float4*)(op + 4) = make_float4(o[4], o[5], o[6], o[7]);
}

// ---------------------------------------------------------------------------
// K3: conv3 (3x3, 16->31) + ReLU + pool -> g_x3 + g_x3p  (PDL consumer)
// ---------------------------------------------------------------------------
__global__ __launch_bounds__(128) void k_conv3(
    const float* __restrict__ k3,      // (3,3,16,31)
    const float* __restrict__ b3)      // (31,)
{
    __shared__ __align__(16) float s_in[10 * 18 * 16];  // 2880 floats
    __shared__ __align__(16) float s_w[9 * 16 * 32];    // 4608 floats (co padded)
    __shared__ float s_b[32];

    int tid = threadIdx.x;
    int bidx = blockIdx.x;
    int b  = bidx >> 5;
    int t  = bidx & 31;                 // 8 ty-tiles x 4 tx-tiles
    int ty0 = (t >> 2) * 4;
    int tx0 = (t & 3) * 8;

    // independent prologue: weight tile (36 LDG/thread)
    for (int i = tid; i < 4608; i += 128) {
        int tap = i >> 9;
        int rem = i & 511;
        int ci = rem >> 5, co = rem & 31;
        s_w[i] = (co < 31) ? k3[tap * 496 + ci * 31 + co] : 0.f;
    }
    if (tid < 32) s_b[tid] = (tid < 31) ? b3[tid] : 0.f;

    cudaGridDependencySynchronize();   // wait for conv2's g_x2

    int iy0 = 2 * ty0 - 1, ix0 = 2 * tx0 - 1;
    for (int p = tid; p < 10 * 18; p += 128) {
        int r = p / 18, c = p % 18;
        int gy = iy0 + r, gx = ix0 + c;
        float* dst = &s_in[p * 16];
        if (gy >= 0 && gy < 64 && gx >= 0 && gx < 64) {
            const float* src = g_x2 + ((size_t)(b * 64 + gy) * 64 + gx) * 16;
#pragma unroll
            for (int q = 0; q < 4; q++)
                *(float4*)(dst + q * 4) = *(const float4*)(src + q * 4);
        } else {
#pragma unroll
            for (int q = 0; q < 4; q++)
                *(float4*)(dst + q * 4) = make_float4(0, 0, 0, 0);
        }
    }
    __syncthreads();

    int pix = tid >> 2, cog = tid & 3, cb = cog * 8;
    int ly = pix >> 3, lx = pix & 7;

    unsigned long long acc2[4][4];
#pragma unroll
    for (int p = 0; p < 4; p++)
#pragma unroll
        for (int k = 0; k < 4; k++) acc2[p][k] = 0ull;

#pragma unroll
    for (int ky = 0; ky < 3; ky++) {
#pragma unroll
        for (int kx = 0; kx < 3; kx++) {
            const float* wtap = &s_w[(ky * 3 + kx) * 512 + cb];
#pragma unroll
            for (int ciq = 0; ciq < 4; ciq++) {
                float iv[4][4];
#pragma unroll
                for (int dy = 0; dy < 2; dy++) {
#pragma unroll
                    for (int dx = 0; dx < 2; dx++) {
                        float4 v = *(const float4*)&s_in[
                            ((2 * ly + dy + ky) * 18 + (2 * lx + dx + kx)) * 16 + ciq * 4];
                        int p = dy * 2 + dx;
                        iv[p][0] = v.x; iv[p][1] = v.y; iv[p][2] = v.z; iv[p][3] = v.w;
                    }
                }
#pragma unroll
                for (int c = 0; c < 4; c++) {
                    ulonglong2 w0 = *(const ulonglong2*)(wtap + (ciq * 4 + c) * 32);
                    ulonglong2 w1 = *(const ulonglong2*)(wtap + (ciq * 4 + c) * 32 + 4);
#pragma unroll
                    for (int p = 0; p < 4; p++) {
                        unsigned long long vv = pk2(iv[p][c], iv[p][c]);
                        fma2(acc2[p][0], vv, w0.x);
                        fma2(acc2[p][1], vv, w0.y);
                        fma2(acc2[p][2], vv, w1.x);
                        fma2(acc2[p][3], vv, w1.y);
                    }
                }
            }
        }
    }

    float m[8];
#pragma unroll
    for (int k = 0; k < 4; k++) {
        float2 p0 = upk2(acc2[0][k]), p1 = upk2(acc2[1][k]);
        float2 p2 = upk2(acc2[2][k]), p3 = upk2(acc2[3][k]);
        m[2 * k]     = fmaxf(fmaxf(p0.x, p1.x), fmaxf(p2.x, p3.x));
        m[2 * k + 1] = fmaxf(fmaxf(p0.y, p1.y), fmaxf(p2.y, p3.y));
    }

    int py = ty0 + ly, px = tx0 + lx;
    int cell = (b * 32 + py) * 32 + px;
    float* op  = g_x3  + (size_t)cell * 31;
    float* opp = g_x3p + (size_t)cell * 32;
    if (cog == 0) opp[0] = 0.f;
#pragma unroll
    for (int k = 0; k < 8; k++) {
        int co = cb + k;
        if (co < 31) {
            float v = fmaxf(m[k] + s_b[co], 0.f);
            op[co] = v;
            opp[co + 1] = v;
        }
    }
}

// ---------------------------------------------------------------------------
// K5: d1 split-K with fused BN affine. 992 blocks, 32-feature slices.
// PDL consumer: weight slice (8 KB DRAM) + BN params stream while conv3 runs.
// ---------------------------------------------------------------------------
__global__ __launch_bounds__(256) void k_d1(
    const float* __restrict__ d1k,
    const float* __restrict__ gamma, const float* __restrict__ beta,
    const float* __restrict__ mean,  const float* __restrict__ var)
{
    __shared__ __align__(16) float ks[32 * 64];   // 8 KB
    __shared__ __align__(16) float gs[16 * 32];   // 2 KB
    __shared__ float s_sc[32], s_sh[32];
    int tid = threadIdx.x;
    int p = blockIdx.x;

    // independent prologue: weight slice + BN scale/shift
    const float4* kbase = (const float4*)(d1k + (size_t)p * 2048);
    float4* ks4 = (float4*)ks;
    ks4[tid]       = kbase[tid];
    ks4[tid + 256] = kbase[tid + 256];

    if (tid < 32) {
        int f = p * 32 + tid;
        float sc = rsqrtf(var[f] + BN_EPS) * gamma[f];
        s_sc[tid] = sc;
        s_sh[tid] = beta[f] - mean[f] * sc;
    }
    __syncthreads();

    cudaGridDependencySynchronize();   // wait for conv3's g_x3

    for (int i = tid; i < 512; i += 256) {
        int bb = i >> 5, ii = i & 31;
        gs[i] = g_x3[bb * 31744 + p * 32 + ii] * s_sc[ii] + s_sh[ii];
    }
    __syncthreads();

    int j = tid & 63, bq = tid >> 6;
    float a0 = 0.f, a1 = 0.f, a2 = 0.f, a3 = 0.f;
#pragma unroll 8
    for (int i = 0; i < 32; i++) {
        float kv = ks[i * 64 + j];
        a0 += gs[bq * 32 + i]        * kv;
        a1 += gs[(bq + 4) * 32 + i]  * kv;
        a2 += gs[(bq + 8) * 32 + i]  * kv;
        a3 += gs[(bq + 12) * 32 + i] * kv;
    }
    g_part[((size_t)p * 16 + bq)      * 64 + j] = a0;
    g_part[((size_t)p * 16 + bq + 4)  * 64 + j] = a1;
    g_part[((size_t)p * 16 + bq + 8)  * 64 + j] = a2;
    g_part[((size_t)p * 16 + bq + 12) * 64 + j] = a3;
}

// ---------------------------------------------------------------------------
// K6: fused head — vectorized reduce of d1 partials + bias + relu, d2, d3.
// ---------------------------------------------------------------------------
__global__ __launch_bounds__(256) void k_head(
    const float* __restrict__ d1b,
    const float* __restrict__ d2k, const float* __restrict__ d2b,
    const float* __restrict__ d3k, const float* __restrict__ d3b)
{
    __shared__ float s_red[16 * 16 * 4];   // [grp][j4][4]
    __shared__ float h1s[64];
    __shared__ float h2s[96];
    int tid = threadIdx.x;
    int b = blockIdx.x;
    int j4 = tid & 15, grp = tid >> 4;

    cudaGridDependencySynchronize();   // wait for k_d1's g_part

    float4 s = make_float4(0.f, 0.f, 0.f, 0.f);
#pragma unroll 8
    for (int p = grp; p < 992; p += 16) {
        float4 v = *(const float4*)&g_part[((size_t)p * 16 + b) * 64 + 4 * j4];
        s.x += v.x; s.y += v.y; s.z += v.z; s.w += v.w;
    }
    *(float4*)&s_red[tid * 4] = s;
    __syncthreads();

    if (tid < 64) {
        int jj4 = tid >> 2, c = tid & 3;
        float v = 0.f;
#pragma unroll
        for (int g = 0; g < 16; g++) v += s_red[(g * 16 + jj4) * 4 + c];
        h1s[tid] = fmaxf(v + d1b[tid], 0.f);
    }
    __syncthreads();

    if (tid < 96) {
        float v = d2b[tid];
#pragma unroll 8
        for (int i = 0; i < 64; i++) v += h1s[i] * d2k[i * 96 + tid];
        h2s[tid] = fmaxf(v, 0.f);
    }
    __syncthreads();

    if (tid < 6) {
        float v = d3b[tid];
#pragma unroll 8
        for (int k = 0; k < 96; k++) v += h2s[k] * d3k[k * 6 + tid];
        g_theta[b * 6 + tid] = v;
    }
}

// ---------------------------------------------------------------------------
// K7: fused grid-gen + bilinear sampler + leaky relu.  (PDL consumer)
// ---------------------------------------------------------------------------
__global__ __launch_bounds__(256) void k_sampler(
    const float* __restrict__ x,       // (16,256,256,1)
    float* __restrict__ out)           // (16,256,256,32)
{
    int bidx = blockIdx.x;             // 8192 = 16 b x 64 row-groups x 8 col-groups
    int b   = bidx >> 9;
    int r   = bidx & 511;
    int oy0 = (r >> 3) * 4;
    int ox0 = (r & 7) * 32;
    int tid = threadIdx.x;
    int tq = tid & 7;
    int pp = tid >> 3;
    int ox = ox0 + pp;

    cudaGridDependencySynchronize();   // wait for k_head's g_theta

    float th0 = g_theta[b * 6 + 0];
    float th1 = g_theta[b * 6 + 1];
    float th2 = g_theta[b * 6 + 2];
    float th3 = g_theta[b * 6 + 3];
    float th4 = g_theta[b * 6 + 4];
    float th5 = g_theta[b * 6 + 5];

    float gx = ((float)ox / 255.f) * 2.f - 1.f;
    const float* xb = x + (size_t)b * 65536;
    const float* xp = g_x3p + (size_t)b * 32768 + 4 * tq;

#pragma unroll
    for (int rr = 0; rr < 4; rr++) {
        int oy = oy0 + rr;
        float gy = ((float)oy / 255.f) * 2.f - 1.f;
        float tgx = gx * th0 + gy * th3 + th2;
        float tgy = gx * th1 + gy * th4 + th5;

        float fx = 0.5f * ((tgx + 1.f) * 255.f);
        float fy = 0.5f * ((tgy + 1.f) * 255.f);
        float x0f = floorf(fx), x1f = x0f + 1.f;
        float y0f = floorf(fy), y1f = y0f + 1.f;
        x0f = fminf(fmaxf(x0f, 0.f), 255.f);
        x1f = fminf(fmaxf(x1f, 0.f), 255.f);
        y0f = fminf(fmaxf(y0f, 0.f), 255.f);
        y1f = fminf(fmaxf(y1f, 0.f), 255.f);
        float wa = (x1f - fx) * (y1f - fy);
        float wb = (x1f - fx) * (fy - y0f);
        float wc = (fx - x0f) * (y1f - fy);
        float wd = (fx - x0f) * (fy - y0f);
        int xi0 = (int)x0f, xi1 = (int)x1f, yi0 = (int)y0f, yi1 = (int)y1f;

        int cy0 = yi0 >> 3, cy1 = yi1 >> 3, cx0 = xi0 >> 3, cx1 = xi1 >> 3;

        float4 va = *(const float4*)(xp + (cy0 * 32 + cx0) * 32);
        float4 vb = *(const float4*)(xp + (cy1 * 32 + cx0) * 32);
        float4 vc = *(const float4*)(xp + (cy0 * 32 + cx1) * 32);
        float4 vd = *(const float4*)(xp + (cy1 * 32 + cx1) * 32);

        float4 val;
        val.x = wa * va.x + wb * vb.x + wc * vc.x + wd * vd.x;
        val.y = wa * va.y + wb * vb.y + wc * vc.y + wd * vd.y;
        val.z = wa * va.z + wb * vb.z + wc * vc.z + wd * vd.z;
        val.w = wa * va.w + wb * vb.w + wc * vc.w + wd * vd.w;

        if (tq == 0) {
            val.x = wa * xb[yi0 * 256 + xi0] + wb * xb[yi1 * 256 + xi0]
                  + wc * xb[yi0 * 256 + xi1] + wd * xb[yi1 * 256 + xi1];
        }

        val.x = (val.x >= 0.f) ? val.x : 0.1f * val.x;
        val.y = (val.y >= 0.f) ? val.y : 0.1f * val.y;
        val.z = (val.z >= 0.f) ? val.z : 0.1f * val.z;
        val.w = (val.w >= 0.f) ? val.w : 0.1f * val.w;

        *(float4*)(out + (((size_t)(b * 256 + oy)) * 256 + ox) * 32 + 4 * tq) = val;
    }
}

// ---------------------------------------------------------------------------
// Launch — consumers launched with Programmatic Stream Serialization so their
// prologues overlap the predecessor's tail.
// ---------------------------------------------------------------------------
static inline void launch_pdl(const void* func, dim3 grid, dim3 block, void** args)
{
    cudaLaunchConfig_t cfg = {};
    cfg.gridDim = grid;
    cfg.blockDim = block;
    cfg.dynamicSmemBytes = 0;
    cfg.stream = 0;
    cudaLaunchAttribute attr[1];
    attr[0].id = cudaLaunchAttributeProgrammaticStreamSerialization;
    attr[0].val.programmaticStreamSerializationAllowed = 1;
    cfg.attrs = attr;
    cfg.numAttrs = 1;
    cudaLaunchKernelExC(&cfg, func, args);
}

extern "C" void kernel_launch(void* const* d_in, const int* in_sizes, int n_in,
                              void* d_out, int out_size)
{
    const float* x       = (const float*)d_in[0];
    const float* conv1_k = (const float*)d_in[1];
    const float* conv1_b = (const float*)d_in[2];
    const float* conv2_k = (const float*)d_in[3];
    const float* conv2_b = (const float*)d_in[4];
    const float* conv3_k = (const float*)d_in[5];
    const float* conv3_b = (const float*)d_in[6];
    const float* bn_gamma = (const float*)d_in[7];
    const float* bn_beta  = (const float*)d_in[8];
    const float* bn_mean  = (const float*)d_in[9];
    const float* bn_var   = (const float*)d_in[10];
    const float* d1_k = (const float*)d_in[11];
    const float* d1_b = (const float*)d_in[12];
    const float* d2_k = (const float*)d_in[13];
    const float* d2_b = (const float*)d_in[14];
    const float* d3_k = (const float*)d_in[15];
    const float* d3_b = (const float*)d_in[16];
    float* out = (float*)d_out;

    k_conv1<<<1024, 256>>>(x, conv1_k, conv1_b);

    {
        void* a[] = { (void*)&conv2_k, (void*)&conv2_b };
        launch_pdl((const void*)k_conv2, dim3(512), dim3(256), a);
    }
    {
        void* a[] = { (void*)&conv3_k, (void*)&conv3_b };
        launch_pdl((const void*)k_conv3, dim3(512), dim3(128), a);
    }
    {
        void* a[] = { (void*)&d1_k, (void*)&bn_gamma, (void*)&bn_beta,
                      (void*)&bn_mean, (void*)&bn_var };
        launch_pdl((const void*)k_d1, dim3(992), dim3(256), a);
    }
    {
        void* a[] = { (void*)&d1_b, (void*)&d2_k, (void*)&d2_b,
                      (void*)&d3_k, (void*)&d3_b };
        launch_pdl((const void*)k_head, dim3(16), dim3(256), a);
    }
    {
        void* a[] = { (void*)&x, (void*)&out };
        launch_pdl((const void*)k_sampler, dim3(8192), dim3(256), a);
    }
}

// round 17
// speedup vs baseline: 1.3469x; 1.1510x over previous
#include <cuda_runtime.h>
#include <math.h>

// ---------------------------------------------------------------------------
// Shapes
// B=16, H=W=256, C=1, LOC_C=31
// x1: 16x128x128x8   x2: 16x64x64x16   x3: 16x32x32x31
// feat = 31744 = 992*32 ; out: 16x256x256x32
// ---------------------------------------------------------------------------

#define BN_EPS 1e-3f

__device__ __align__(256) float g_x1[16 * 128 * 128 * 8];     // 8 MB
__device__ __align__(256) float g_x2[16 * 64 * 64 * 16];      // 4 MB
__device__ __align__(256) float g_x3[16 * 32 * 32 * 31];      // 2 MB
__device__ __align__(256) float g_x3p[16 * 32 * 32 * 32];     // 2 MB
__device__ __align__(256) float g_part[992 * 16 * 64];        // 4 MB
__device__ __align__(256) float g_theta[16 * 6];

// ---- packed f32x2 helpers (Blackwell FFMA2) --------------------------------
__device__ __forceinline__ unsigned long long pk2(float a, float b) {
    unsigned long long r;
    asm("mov.b64 %0, {%1, %2};" : "=l"(r) : "f"(a), "f"(b));
    return r;
}
__device__ __forceinline__ void fma2(unsigned long long& d,
                                     unsigned long long a, unsigned long long b) {
    asm("fma.rn.f32x2 %0, %1, %2, %0;" : "+l"(d) : "l"(a), "l"(b));
}
__device__ __forceinline__ float2 upk2(unsigned long long v) {
    float2 r;
    asm("mov.b64 {%0, %1}, %2;" : "=f"(r.x), "=f"(r.y) : "l"(v));
    return r;
}

// padded pixel strides (floats) — collision-free bank staggering
#define P2 12   // conv2: 8 data floats + 4 pad  (48 B)
#define P3 20   // conv3: 16 data floats + 4 pad (80 B)

// ---------------------------------------------------------------------------
// K1: conv1 (3x3, 1->8, SAME) + ReLU + maxpool2  -> g_x1
// ---------------------------------------------------------------------------
__global__ __launch_bounds__(256) void k_conv1(
    const float* __restrict__ x,
    const float* __restrict__ k1,
    const float* __restrict__ b1)
{
    __shared__ float s_x[34 * 34];
    __shared__ __align__(16) float s_w[72];
    __shared__ float s_b[8];
    int tid = threadIdx.x;
    int bidx = blockIdx.x;
    int b  = bidx >> 6;
    int t  = bidx & 63;
    int ty0 = (t >> 3) * 16;
    int tx0 = (t & 7) * 16;

    if (tid < 72) s_w[tid] = k1[tid];
    if (tid < 8)  s_b[tid] = b1[tid];

    const float* xb = x + b * 65536;
    int iy0 = 2 * ty0 - 1, ix0 = 2 * tx0 - 1;
    for (int p = tid; p < 34 * 34; p += 256) {
        int r = p / 34, c = p % 34;
        int gy = iy0 + r, gx = ix0 + c;
        s_x[p] = (gy >= 0 && gy < 256 && gx >= 0 && gx < 256)
                 ? xb[gy * 256 + gx] : 0.f;
    }
    __syncthreads();

    int ly = tid >> 4, lx = tid & 15;

    float win[4][4];
#pragma unroll
    for (int r = 0; r < 4; r++)
#pragma unroll
        for (int c = 0; c < 4; c++)
            win[r][c] = s_x[(2 * ly + r) * 34 + (2 * lx + c)];

    unsigned long long acc2[4][4];
#pragma unroll
    for (int p = 0; p < 4; p++)
#pragma unroll
        for (int k = 0; k < 4; k++) acc2[p][k] = 0ull;

#pragma unroll
    for (int ky = 0; ky < 3; ky++) {
#pragma unroll
        for (int kx = 0; kx < 3; kx++) {
            ulonglong2 wa = *(const ulonglong2*)&s_w[(ky * 3 + kx) * 8];
            ulonglong2 wb = *(const ulonglong2*)&s_w[(ky * 3 + kx) * 8 + 4];
#pragma unroll
            for (int dy = 0; dy < 2; dy++) {
#pragma unroll
                for (int dx = 0; dx < 2; dx++) {
                    float v = win[dy + ky][dx + kx];
                    unsigned long long vv = pk2(v, v);
                    int p = dy * 2 + dx;
                    fma2(acc2[p][0], vv, wa.x);
                    fma2(acc2[p][1], vv, wa.y);
                    fma2(acc2[p][2], vv, wb.x);
                    fma2(acc2[p][3], vv, wb.y);
                }
            }
        }
    }

    float o[8];
#pragma unroll
    for (int k = 0; k < 4; k++) {
        float2 p0 = upk2(acc2[0][k]), p1 = upk2(acc2[1][k]);
        float2 p2 = upk2(acc2[2][k]), p3 = upk2(acc2[3][k]);
        float mx = fmaxf(fmaxf(p0.x, p1.x), fmaxf(p2.x, p3.x));
        float my = fmaxf(fmaxf(p0.y, p1.y), fmaxf(p2.y, p3.y));
        o[2 * k]     = fmaxf(mx + s_b[2 * k], 0.f);
        o[2 * k + 1] = fmaxf(my + s_b[2 * k + 1], 0.f);
    }
    int py = ty0 + ly, px = tx0 + lx;
    float* op = g_x1 + ((size_t)(b * 128 + py) * 128 + px) * 8;
    *(float4*)op       = make_float4(o[0], o[1], o[2], o[3]);
    *(float4*)(op + 4) = make_float4(o[4], o[5], o[6], o[7]);
}

// ---------------------------------------------------------------------------
// K2: conv2 (3x3, 8->16) + ReLU + pool -> g_x2  (PDL consumer of conv1)
// s_in pixel stride padded to P2=12 floats (bank stagger, 8->4 way).
// ---------------------------------------------------------------------------
__global__ __launch_bounds__(256) void k_conv2(
    const float* __restrict__ k2,      // (3,3,8,16)
    const float* __restrict__ b2)      // (16,)
{
    __shared__ __align__(16) float s_in[18 * 34 * P2];   // 7344 floats
    __shared__ __align__(16) float s_w[1152];
    __shared__ float s_b[16];

    int tid = threadIdx.x;
    int bidx = blockIdx.x;
    int b  = bidx >> 5;
    int t  = bidx & 31;                 // 8 ty-tiles x 4 tx-tiles
    int ty0 = (t >> 2) * 8;
    int tx0 = (t & 3) * 16;

    // independent prologue: weights
    for (int i = tid; i < 1152; i += 256) s_w[i] = k2[i];
    if (tid < 16) s_b[tid] = b2[tid];

    cudaGridDependencySynchronize();   // wait for conv1's g_x1

    int iy0 = 2 * ty0 - 1, ix0 = 2 * tx0 - 1;
    for (int p = tid; p < 18 * 34; p += 256) {
        int r = p / 34, c = p % 34;
        int gy = iy0 + r, gx = ix0 + c;
        float* dst = &s_in[p * P2];
        if (gy >= 0 && gy < 128 && gx >= 0 && gx < 128) {
            const float* src = g_x1 + ((size_t)(b * 128 + gy) * 128 + gx) * 8;
            *(float4*)dst       = *(const float4*)src;
            *(float4*)(dst + 4) = *(const float4*)(src + 4);
        } else {
            *(float4*)dst       = make_float4(0, 0, 0, 0);
            *(float4*)(dst + 4) = make_float4(0, 0, 0, 0);
        }
    }
    __syncthreads();

    int pix = tid >> 1, cog = tid & 1, cb = cog * 8;
    int ly = pix >> 4, lx = pix & 15;

    unsigned long long acc2[4][4];     // [pos][co-pair of 8]
#pragma unroll
    for (int p = 0; p < 4; p++)
#pragma unroll
        for (int k = 0; k < 4; k++) acc2[p][k] = 0ull;

#pragma unroll
    for (int ky = 0; ky < 3; ky++) {
#pragma unroll
        for (int kx = 0; kx < 3; kx++) {
            const float* wtap = &s_w[(ky * 3 + kx) * 128 + cb];
#pragma unroll
            for (int ciq = 0; ciq < 2; ciq++) {
                float iv[4][4];
#pragma unroll
                for (int dy = 0; dy < 2; dy++) {
#pragma unroll
                    for (int dx = 0; dx < 2; dx++) {
                        int q = (2 * ly + dy + ky) * 34 + (2 * lx + dx + kx);
                        float4 v = *(const float4*)&s_in[q * P2 + ciq * 4];
                        int p = dy * 2 + dx;
                        iv[p][0] = v.x; iv[p][1] = v.y; iv[p][2] = v.z; iv[p][3] = v.w;
                    }
                }
#pragma unroll
                for (int c = 0; c < 4; c++) {
                    ulonglong2 w0 = *(const ulonglong2*)(wtap + (ciq * 4 + c) * 16);
                    ulonglong2 w1 = *(const ulonglong2*)(wtap + (ciq * 4 + c) * 16 + 4);
#pragma unroll
                    for (int p = 0; p < 4; p++) {
                        unsigned long long vv = pk2(iv[p][c], iv[p][c]);
                        fma2(acc2[p][0], vv, w0.x);
                        fma2(acc2[p][1], vv, w0.y);
                        fma2(acc2[p][2], vv, w1.x);
                        fma2(acc2[p][3], vv, w1.y);
                    }
                }
            }
        }
    }

    float o[8];
#pragma unroll
    for (int k = 0; k < 4; k++) {
        float2 p0 = upk2(acc2[0][k]), p1 = upk2(acc2[1][k]);
        float2 p2 = upk2(acc2[2][k]), p3 = upk2(acc2[3][k]);
        float mx = fmaxf(fmaxf(p0.x, p1.x), fmaxf(p2.x, p3.x));
        float my = fmaxf(fmaxf(p0.y, p1.y), fmaxf(p2.y, p3.y));
        o[2 * k]     = fmaxf(mx + s_b[cb + 2 * k], 0.f);
        o[2 * k + 1] = fmaxf(my + s_b[cb + 2 * k + 1], 0.f);
    }

    int py = ty0 + ly, px = tx0 + lx;
    float* op = g_x2 + ((size_t)(b * 64 + py) * 64 + px) * 16 + cb;
    *(float4*)op       = make_float4(o[0], o[1], o[2], o[3]);
    *(float4*)(op + 4) = make_float4(o[4], o[5], o[6], o[7]);
}

// ---------------------------------------------------------------------------
// K3: conv3 (3x3, 16->31) + ReLU + pool -> g_x3 + g_x3p  (PDL consumer)
// s_in pixel stride padded to P3=20 floats (bank stagger, 8->2 way).
// ---------------------------------------------------------------------------
__global__ __launch_bounds__(128) void k_conv3(
    const float* __restrict__ k3,      // (3,3,16,31)
    const float* __restrict__ b3)      // (31,)
{
    __shared__ __align__(16) float s_in[10 * 18 * P3];   // 3600 floats
    __shared__ __align__(16) float s_w[9 * 16 * 32];     // co padded to 32
    __shared__ float s_b[32];

    int tid = threadIdx.x;
    int bidx = blockIdx.x;
    int b  = bidx >> 5;
    int t  = bidx & 31;                 // 8 ty-tiles x 4 tx-tiles
    int ty0 = (t >> 2) * 4;
    int tx0 = (t & 3) * 8;

    // independent prologue: weight tile
    for (int i = tid; i < 4608; i += 128) {
        int tap = i >> 9;
        int rem = i & 511;
        int ci = rem >> 5, co = rem & 31;
        s_w[i] = (co < 31) ? k3[tap * 496 + ci * 31 + co] : 0.f;
    }
    if (tid < 32) s_b[tid] = (tid < 31) ? b3[tid] : 0.f;

    cudaGridDependencySynchronize();   // wait for conv2's g_x2

    int iy0 = 2 * ty0 - 1, ix0 = 2 * tx0 - 1;
    for (int p = tid; p < 10 * 18; p += 128) {
        int r = p / 18, c = p % 18;
        int gy = iy0 + r, gx = ix0 + c;
        float* dst = &s_in[p * P3];
        if (gy >= 0 && gy < 64 && gx >= 0 && gx < 64) {
            const float* src = g_x2 + ((size_t)(b * 64 + gy) * 64 + gx) * 16;
#pragma unroll
            for (int q = 0; q < 4; q++)
                *(float4*)(dst + q * 4) = *(const float4*)(src + q * 4);
        } else {
#pragma unroll
            for (int q = 0; q < 4; q++)
                *(float4*)(dst + q * 4) = make_float4(0, 0, 0, 0);
        }
    }
    __syncthreads();

    int pix = tid >> 2, cog = tid & 3, cb = cog * 8;
    int ly = pix >> 3, lx = pix & 7;

    unsigned long long acc2[4][4];
#pragma unroll
    for (int p = 0; p < 4; p++)
#pragma unroll
        for (int k = 0; k < 4; k++) acc2[p][k] = 0ull;

#pragma unroll
    for (int ky = 0; ky < 3; ky++) {
#pragma unroll
        for (int kx = 0; kx < 3; kx++) {
            const float* wtap = &s_w[(ky * 3 + kx) * 512 + cb];
#pragma unroll
            for (int ciq = 0; ciq < 4; ciq++) {
                float iv[4][4];
#pragma unroll
                for (int dy = 0; dy < 2; dy++) {
#pragma unroll
                    for (int dx = 0; dx < 2; dx++) {
                        int q = (2 * ly + dy + ky) * 18 + (2 * lx + dx + kx);
                        float4 v = *(const float4*)&s_in[q * P3 + ciq * 4];
                        int p = dy * 2 + dx;
                        iv[p][0] = v.x; iv[p][1] = v.y; iv[p][2] = v.z; iv[p][3] = v.w;
                    }
                }
#pragma unroll
                for (int c = 0; c < 4; c++) {
                    ulonglong2 w0 = *(const ulonglong2*)(wtap + (ciq * 4 + c) * 32);
                    ulonglong2 w1 = *(const ulonglong2*)(wtap + (ciq * 4 + c) * 32 + 4);
#pragma unroll
                    for (int p = 0; p < 4; p++) {
                        unsigned long long vv = pk2(iv[p][c], iv[p][c]);
                        fma2(acc2[p][0], vv, w0.x);
                        fma2(acc2[p][1], vv, w0.y);
                        fma2(acc2[p][2], vv, w1.x);
                        fma2(acc2[p][3], vv, w1.y);
                    }
                }
            }
        }
    }

    float m[8];
#pragma unroll
    for (int k = 0; k < 4; k++) {
        float2 p0 = upk2(acc2[0][k]), p1 = upk2(acc2[1][k]);
        float2 p2 = upk2(acc2[2][k]), p3 = upk2(acc2[3][k]);
        m[2 * k]     = fmaxf(fmaxf(p0.x, p1.x), fmaxf(p2.x, p3.x));
        m[2 * k + 1] = fmaxf(fmaxf(p0.y, p1.y), fmaxf(p2.y, p3.y));
    }

    int py = ty0 + ly, px = tx0 + lx;
    int cell = (b * 32 + py) * 32 + px;
    float* op  = g_x3  + (size_t)cell * 31;
    float* opp = g_x3p + (size_t)cell * 32;
    if (cog == 0) opp[0] = 0.f;
#pragma unroll
    for (int k = 0; k < 8; k++) {
        int co = cb + k;
        if (co < 31) {
            float v = fmaxf(m[k] + s_b[co], 0.f);
            op[co] = v;
            opp[co + 1] = v;
        }
    }
}

// ---------------------------------------------------------------------------
// K5: d1 split-K with fused BN affine. 992 blocks, 32-feature slices.
// PDL consumer: weight slice + BN params stream while conv3 runs.
// ---------------------------------------------------------------------------
__global__ __launch_bounds__(256) void k_d1(
    const float* __restrict__ d1k,
    const float* __restrict__ gamma, const float* __restrict__ beta,
    const float* __restrict__ mean,  const float* __restrict__ var)
{
    __shared__ __align__(16) float ks[32 * 64];   // 8 KB
    __shared__ __align__(16) float gs[16 * 32];   // 2 KB
    __shared__ float s_sc[32], s_sh[32];
    int tid = threadIdx.x;
    int p = blockIdx.x;

    const float4* kbase = (const float4*)(d1k + (size_t)p * 2048);
    float4* ks4 = (float4*)ks;
    ks4[tid]       = kbase[tid];
    ks4[tid + 256] = kbase[tid + 256];

    if (tid < 32) {
        int f = p * 32 + tid;
        float sc = rsqrtf(var[f] + BN_EPS) * gamma[f];
        s_sc[tid] = sc;
        s_sh[tid] = beta[f] - mean[f] * sc;
    }
    __syncthreads();

    cudaGridDependencySynchronize();   // wait for conv3's g_x3

    for (int i = tid; i < 512; i += 256) {
        int bb = i >> 5, ii = i & 31;
        gs[i] = g_x3[bb * 31744 + p * 32 + ii] * s_sc[ii] + s_sh[ii];
    }
    __syncthreads();

    int j = tid & 63, bq = tid >> 6;
    float a0 = 0.f, a1 = 0.f, a2 = 0.f, a3 = 0.f;
#pragma unroll 8
    for (int i = 0; i < 32; i++) {
        float kv = ks[i * 64 + j];
        a0 += gs[bq * 32 + i]        * kv;
        a1 += gs[(bq + 4) * 32 + i]  * kv;
        a2 += gs[(bq + 8) * 32 + i]  * kv;
        a3 += gs[(bq + 12) * 32 + i] * kv;
    }
    g_part[((size_t)p * 16 + bq)      * 64 + j] = a0;
    g_part[((size_t)p * 16 + bq + 4)  * 64 + j] = a1;
    g_part[((size_t)p * 16 + bq + 8)  * 64 + j] = a2;
    g_part[((size_t)p * 16 + bq + 12) * 64 + j] = a3;
}

// ---------------------------------------------------------------------------
// K6: fused head — vectorized reduce of d1 partials + bias + relu, d2, d3.
// ---------------------------------------------------------------------------
__global__ __launch_bounds__(256) void k_head(
    const float* __restrict__ d1b,
    const float* __restrict__ d2k, const float* __restrict__ d2b,
    const float* __restrict__ d3k, const float* __restrict__ d3b)
{
    __shared__ float s_red[16 * 16 * 4];   // [grp][j4][4]
    __shared__ float h1s[64];
    __shared__ float h2s[96];
    int tid = threadIdx.x;
    int b = blockIdx.x;
    int j4 = tid & 15, grp = tid >> 4;

    cudaGridDependencySynchronize();   // wait for k_d1's g_part

    float4 s = make_float4(0.f, 0.f, 0.f, 0.f);
#pragma unroll 8
    for (int p = grp; p < 992; p += 16) {
        float4 v = *(const float4*)&g_part[((size_t)p * 16 + b) * 64 + 4 * j4];
        s.x += v.x; s.y += v.y; s.z += v.z; s.w += v.w;
    }
    *(float4*)&s_red[tid * 4] = s;
    __syncthreads();

    if (tid < 64) {
        int jj4 = tid >> 2, c = tid & 3;
        float v = 0.f;
#pragma unroll
        for (int g = 0; g < 16; g++) v += s_red[(g * 16 + jj4) * 4 + c];
        h1s[tid] = fmaxf(v + d1b[tid], 0.f);
    }
    __syncthreads();

    if (tid < 96) {
        float v = d2b[tid];
#pragma unroll 8
        for (int i = 0; i < 64; i++) v += h1s[i] * d2k[i * 96 + tid];
        h2s[tid] = fmaxf(v, 0.f);
    }
    __syncthreads();

    if (tid < 6) {
        float v = d3b[tid];
#pragma unroll 8
        for (int k = 0; k < 96; k++) v += h2s[k] * d3k[k * 6 + tid];
        g_theta[b * 6 + tid] = v;
    }
}

// ---------------------------------------------------------------------------
// K7: fused grid-gen + bilinear sampler + leaky relu.  (PDL consumer)
// Output stores use streaming hint (__stcs) to protect L2-resident g_x3p.
// ---------------------------------------------------------------------------
__global__ __launch_bounds__(256) void k_sampler(
    const float* __restrict__ x,       // (16,256,256,1)
    float* __restrict__ out)           // (16,256,256,32)
{
    int bidx = blockIdx.x;             // 8192 = 16 b x 64 row-groups x 8 col-groups
    int b   = bidx >> 9;
    int r   = bidx & 511;
    int oy0 = (r >> 3) * 4;
    int ox0 = (r & 7) * 32;
    int tid = threadIdx.x;
    int tq = tid & 7;
    int pp = tid >> 3;
    int ox = ox0 + pp;

    cudaGridDependencySynchronize();   // wait for k_head's g_theta

    float th0 = g_theta[b * 6 + 0];
    float th1 = g_theta[b * 6 + 1];
    float th2 = g_theta[b * 6 + 2];
    float th3 = g_theta[b * 6 + 3];
    float th4 = g_theta[b * 6 + 4];
    float th5 = g_theta[b * 6 + 5];

    float gx = ((float)ox / 255.f) * 2.f - 1.f;
    const float* xb = x + (size_t)b * 65536;
    const float* xp = g_x3p + (size_t)b * 32768 + 4 * tq;

#pragma unroll
    for (int rr = 0; rr < 4; rr++) {
        int oy = oy0 + rr;
        float gy = ((float)oy / 255.f) * 2.f - 1.f;
        float tgx = gx * th0 + gy * th3 + th2;
        float tgy = gx * th1 + gy * th4 + th5;

        float fx = 0.5f * ((tgx + 1.f) * 255.f);
        float fy = 0.5f * ((tgy + 1.f) * 255.f);
        float x0f = floorf(fx), x1f = x0f + 1.f;
        float y0f = floorf(fy), y1f = y0f + 1.f;
        x0f = fminf(fmaxf(x0f, 0.f), 255.f);
        x1f = fminf(fmaxf(x1f, 0.f), 255.f);
        y0f = fminf(fmaxf(y0f, 0.f), 255.f);
        y1f = fminf(fmaxf(y1f, 0.f), 255.f);
        float wa = (x1f - fx) * (y1f - fy);
        float wb = (x1f - fx) * (fy - y0f);
        float wc = (fx - x0f) * (y1f - fy);
        float wd = (fx - x0f) * (fy - y0f);
        int xi0 = (int)x0f, xi1 = (int)x1f, yi0 = (int)y0f, yi1 = (int)y1f;

        int cy0 = yi0 >> 3, cy1 = yi1 >> 3, cx0 = xi0 >> 3, cx1 = xi1 >> 3;

        float4 va = *(const float4*)(xp + (cy0 * 32 + cx0) * 32);
        float4 vb = *(const float4*)(xp + (cy1 * 32 + cx0) * 32);
        float4 vc = *(const float4*)(xp + (cy0 * 32 + cx1) * 32);
        float4 vd = *(const float4*)(xp + (cy1 * 32 + cx1) * 32);

        float4 val;
        val.x = wa * va.x + wb * vb.x + wc * vc.x + wd * vd.x;
        val.y = wa * va.y + wb * vb.y + wc * vc.y + wd * vd.y;
        val.z = wa * va.z + wb * vb.z + wc * vc.z + wd * vd.z;
        val.w = wa * va.w + wb * vb.w + wc * vc.w + wd * vd.w;

        if (tq == 0) {
            val.x = wa * xb[yi0 * 256 + xi0] + wb * xb[yi1 * 256 + xi0]
                  + wc * xb[yi0 * 256 + xi1] + wd * xb[yi1 * 256 + xi1];
        }

        val.x = (val.x >= 0.f) ? val.x : 0.1f * val.x;
        val.y = (val.y >= 0.f) ? val.y : 0.1f * val.y;
        val.z = (val.z >= 0.f) ? val.z : 0.1f * val.z;
        val.w = (val.w >= 0.f) ? val.w : 0.1f * val.w;

        __stcs((float4*)(out + (((size_t)(b * 256 + oy)) * 256 + ox) * 32 + 4 * tq), val);
    }
}

// ---------------------------------------------------------------------------
// Launch — consumers launched with Programmatic Stream Serialization so their
// prologues overlap the predecessor's tail.
// ---------------------------------------------------------------------------
static inline void launch_pdl(const void* func, dim3 grid, dim3 block, void** args)
{
    cudaLaunchConfig_t cfg = {};
    cfg.gridDim = grid;
    cfg.blockDim = block;
    cfg.dynamicSmemBytes = 0;
    cfg.stream = 0;
    cudaLaunchAttribute attr[1];
    attr[0].id = cudaLaunchAttributeProgrammaticStreamSerialization;
    attr[0].val.programmaticStreamSerializationAllowed = 1;
    cfg.attrs = attr;
    cfg.numAttrs = 1;
    cudaLaunchKernelExC(&cfg, func, args);
}

extern "C" void kernel_launch(void* const* d_in, const int* in_sizes, int n_in,
                              void* d_out, int out_size)
{
    const float* x       = (const float*)d_in[0];
    const float* conv1_k = (const float*)d_in[1];
    const float* conv1_b = (const float*)d_in[2];
    const float* conv2_k = (const float*)d_in[3];
    const float* conv2_b = (const float*)d_in[4];
    const float* conv3_k = (const float*)d_in[5];
    const float* conv3_b = (const float*)d_in[6];
    const float* bn_gamma = (const float*)d_in[7];
    const float* bn_beta  = (const float*)d_in[8];
    const float* bn_mean  = (const float*)d_in[9];
    const float* bn_var   = (const float*)d_in[10];
    const float* d1_k = (const float*)d_in[11];
    const float* d1_b = (const float*)d_in[12];
    const float* d2_k = (const float*)d_in[13];
    const float* d2_b = (const float*)d_in[14];
    const float* d3_k = (const float*)d_in[15];
    const float* d3_b = (const float*)d_in[16];
    float* out = (float*)d_out;

    k_conv1<<<1024, 256>>>(x, conv1_k, conv1_b);

    {
        void* a[] = { (void*)&conv2_k, (void*)&conv2_b };
        launch_pdl((const void*)k_conv2, dim3(512), dim3(256), a);
    }
    {
        void* a[] = { (void*)&conv3_k, (void*)&conv3_b };
        launch_pdl((const void*)k_conv3, dim3(512), dim3(128), a);
    }
    {
        void* a[] = { (void*)&d1_k, (void*)&bn_gamma, (void*)&bn_beta,
                      (void*)&bn_mean, (void*)&bn_var };
        launch_pdl((const void*)k_d1, dim3(992), dim3(256), a);
    }
    {
        void* a[] = { (void*)&d1_b, (void*)&d2_k, (void*)&d2_b,
                      (void*)&d3_k, (void*)&d3_b };
        launch_pdl((const void*)k_head, dim3(16), dim3(256), a);
    }
    {
        void* a[] = { (void*)&x, (void*)&out };
        launch_pdl((const void*)k_sampler, dim3(8192), dim3(256), a);
    }
}